// round 7
// baseline (speedup 1.0000x reference)
#include <cuda_runtime.h>
#include <cuda_bf16.h>
#include <math.h>

#define NTOK 8192
#define DIM  1024
#define DLS  128
#define NE   8
#define HDV  32
#define TT   2048
#define BBATCH 4
#define S9   9

// ---------------- scratch ----------------------------------------------------
__device__ float g_ef[NTOK * DIM];
__device__ float g_xmean[BBATCH * DIM];
__device__ float g_gctx[BBATCH * DLS];
__device__ float g_rq[BBATCH * DLS];
__device__ float g_k0[BBATCH * DLS];
__device__ float g_v0[BBATCH * DLS];
__device__ float g_probs[NTOK * NE];
__device__ float g_coef[NTOK * NE];
__device__ float g_wt_in[DLS * 384];
__device__ float g_wt_out[DLS * DLS];
__device__ float g_wt_rk[DLS * DLS];

__device__ __align__(16) __nv_bfloat16 g_xh[NTOK * DIM];
__device__ __align__(16) __nv_bfloat16 g_xm[NTOK * DIM];
__device__ __align__(16) __nv_bfloat16 g_xl[NTOK * DIM];
__device__ __align__(16) __nv_bfloat16 g_w1h[DIM * DIM];
__device__ __align__(16) __nv_bfloat16 g_w1m[DIM * DIM];
__device__ __align__(16) __nv_bfloat16 g_w1l[DIM * DIM];
__device__ __align__(16) __nv_bfloat16 g_ah[NTOK * DIM];
__device__ __align__(16) __nv_bfloat16 g_al[NTOK * DIM];
__device__ __align__(16) __nv_bfloat16 g_w2h[DIM * DIM];
__device__ __align__(16) __nv_bfloat16 g_w2l[DIM * DIM];

__device__ __forceinline__ float gelu_f(float x) {
    return 0.5f * x * (1.0f + erff(x * 0.70710678118654752440f));
}

// ---------------- PTX helpers ------------------------------------------------
__device__ __forceinline__ unsigned smem_u32(const void* p) {
    unsigned a;
    asm("{ .reg .u64 t; cvta.to.shared.u64 t, %1; cvt.u32.u64 %0, t; }"
        : "=r"(a) : "l"(p));
    return a;
}
__device__ __forceinline__ void cp16(unsigned d, const void* g) {
    asm volatile("cp.async.cg.shared.global [%0], [%1], 16;" :: "r"(d), "l"(g));
}
__device__ __forceinline__ void ldm_x4(unsigned* r, unsigned addr) {
    asm volatile("ldmatrix.sync.aligned.m8n8.x4.shared.b16 {%0,%1,%2,%3}, [%4];"
                 : "=r"(r[0]), "=r"(r[1]), "=r"(r[2]), "=r"(r[3]) : "r"(addr));
}
__device__ __forceinline__ void mma16816(float* d, const unsigned* a,
                                         unsigned b0, unsigned b1) {
    asm volatile(
        "mma.sync.aligned.m16n8k16.row.col.f32.bf16.bf16.f32 "
        "{%0,%1,%2,%3}, {%4,%5,%6,%7}, {%8,%9}, {%0,%1,%2,%3};"
        : "+f"(d[0]), "+f"(d[1]), "+f"(d[2]), "+f"(d[3])
        : "r"(a[0]), "r"(a[1]), "r"(a[2]), "r"(a[3]), "r"(b0), "r"(b1));
}
// packed f32x2 (sm_100+)
__device__ __forceinline__ void fma2(unsigned long long& d, unsigned long long a,
                                     unsigned long long b) {
    asm("fma.rn.f32x2 %0, %1, %2, %0;" : "+l"(d) : "l"(a), "l"(b));
}
__device__ __forceinline__ unsigned long long bcast2(float x) {
    unsigned long long r;
    asm("mov.b64 %0, {%1, %1};" : "=l"(r) : "f"(x));
    return r;
}
__device__ __forceinline__ void unpack2(float& lo, float& hi,
                                        unsigned long long v) {
    asm("mov.b64 {%0, %1}, %2;" : "=f"(lo), "=f"(hi) : "l"(v));
}

// ---------------- HMMA GEMM (3-stage cp.async pipeline) ----------------------
template <int NP>
__device__ __forceinline__ void gemm_mma(
    const __nv_bfloat16* const* Al, const __nv_bfloat16* const* Bl,
    const signed char* pi, const signed char* pj, float* __restrict__ C) {
    extern __shared__ __align__(128) char smem[];
    int tid = threadIdx.x, lane = tid & 31, warp = tid >> 5;
    int n0 = blockIdx.x * 128, m0 = blockIdx.y * 128;
    int wm = (warp & 1) * 64, wn = (warp >> 1) * 32;
    unsigned sbase = smem_u32(smem);

    float acc[4][4][4] = {};

    auto load = [&](int t, int s) {
        const __nv_bfloat16* A = Al[pi[t >> 4]];
        const __nv_bfloat16* B = Bl[pj[t >> 4]];
        int k0 = (t & 15) * 64;
        unsigned sa = sbase + (unsigned)s * 32768u, sb = sa + 16384u;
#pragma unroll
        for (int i = 0; i < 4; i++) {
            int cid = tid + (i << 8);
            int r = cid >> 3, c = cid & 7;
            unsigned off = (unsigned)(r * 128 + ((c ^ (r & 7)) << 4));
            cp16(sa + off, (const char*)(A + (size_t)(m0 + r) * 1024 + k0) + c * 16);
            cp16(sb + off, (const char*)(B + (size_t)(n0 + r) * 1024 + k0) + c * 16);
        }
        asm volatile("cp.async.commit_group;" ::: "memory");
    };

    constexpr int T = NP * 16;
    load(0, 0);
    load(1, 1);
#pragma unroll 1
    for (int t = 0; t < T; t++) {
        asm volatile("cp.async.wait_group 1;" ::: "memory");
        __syncthreads();
        if (t + 2 < T) load(t + 2, (t + 2) % 3);
        unsigned sa = sbase + (unsigned)(t % 3) * 32768u, sb = sa + 16384u;
#pragma unroll
        for (int ks = 0; ks < 4; ks++) {
            int clo = ks * 2;
            unsigned a[4][4], b[2][4];
#pragma unroll
            for (int g = 0; g < 4; g++) {
                int row = wm + g * 16 + (lane & 15);
                int c = clo + (lane >> 4);
                ldm_x4(a[g], sa + row * 128 + ((c ^ (row & 7)) << 4));
            }
#pragma unroll
            for (int h = 0; h < 2; h++) {
                int row = wn + h * 16 + ((lane >> 4) << 3) + (lane & 7);
                int c = clo + ((lane >> 3) & 1);
                ldm_x4(b[h], sb + row * 128 + ((c ^ (row & 7)) << 4));
            }
#pragma unroll
            for (int i = 0; i < 4; i++)
#pragma unroll
                for (int j = 0; j < 4; j++) {
                    const unsigned* bf = &b[j >> 1][(j & 1) * 2];
                    mma16816(acc[i][j], a[i], bf[0], bf[1]);
                }
        }
    }

#pragma unroll
    for (int i = 0; i < 4; i++) {
        int row = m0 + wm + i * 16 + (lane >> 2);
#pragma unroll
        for (int j = 0; j < 4; j++) {
            int col = n0 + wn + j * 8 + (lane & 3) * 2;
            *(float2*)(C + (size_t)row * 1024 + col) =
                make_float2(acc[i][j][0], acc[i][j][1]);
            *(float2*)(C + (size_t)(row + 8) * 1024 + col) =
                make_float2(acc[i][j][2], acc[i][j][3]);
        }
    }
}

__global__ void __launch_bounds__(256) k_gemm1() {
    const __nv_bfloat16* A[3] = {g_xh, g_xm, g_xl};
    const __nv_bfloat16* B[3] = {g_w1h, g_w1m, g_w1l};
    const signed char pi[6] = {0, 0, 1, 0, 1, 2};
    const signed char pj[6] = {0, 1, 0, 2, 1, 0};
    gemm_mma<6>(A, B, pi, pj, g_ef);
}
__global__ void __launch_bounds__(256) k_gemm2(float* __restrict__ C) {
    const __nv_bfloat16* A[2] = {g_ah, g_al};
    const __nv_bfloat16* B[2] = {g_w2h, g_w2l};
    const signed char pi[3] = {0, 0, 1};
    const signed char pj[3] = {0, 1, 0};
    gemm_mma<3>(A, B, pi, pj, C);
}

// ---------------- split kernels ----------------------------------------------
__device__ __forceinline__ unsigned pack2b(__nv_bfloat16 a, __nv_bfloat16 b) {
    return (unsigned)__bfloat16_as_ushort(b) << 16 | __bfloat16_as_ushort(a);
}
__device__ __forceinline__ void split3_store(
    const float* __restrict__ src, __nv_bfloat16* dh, __nv_bfloat16* dm,
    __nv_bfloat16* dl, size_t i) {
    float4 v = ((const float4*)src)[i];
    float vs[4] = {v.x, v.y, v.z, v.w};
    __nv_bfloat16 h[4], m[4], l[4];
#pragma unroll
    for (int q = 0; q < 4; q++) {
        h[q] = __float2bfloat16(vs[q]);
        float r1 = vs[q] - __bfloat162float(h[q]);
        m[q] = __float2bfloat16(r1);
        l[q] = __float2bfloat16(r1 - __bfloat162float(m[q]));
    }
    ((uint2*)dh)[i] = make_uint2(pack2b(h[0], h[1]), pack2b(h[2], h[3]));
    ((uint2*)dm)[i] = make_uint2(pack2b(m[0], m[1]), pack2b(m[2], m[3]));
    ((uint2*)dl)[i] = make_uint2(pack2b(l[0], l[1]), pack2b(l[2], l[3]));
}
__global__ void k_split3_x(const float* __restrict__ x) {
    size_t i = (size_t)blockIdx.x * blockDim.x + threadIdx.x;
    split3_store(x, g_xh, g_xm, g_xl, i);
}
__global__ void k_split3_w(const float* __restrict__ w) {
    size_t i = (size_t)blockIdx.x * blockDim.x + threadIdx.x;
    split3_store(w, g_w1h, g_w1m, g_w1l, i);
}
__global__ void k_tsplit2_wup(const float* __restrict__ wup) {
    __shared__ float tile[32][33];
    int k0 = blockIdx.y * 32, m0 = blockIdx.x * 32;
    int tx = threadIdx.x, ty = threadIdx.y;
#pragma unroll
    for (int i = 0; i < 32; i += 8)
        tile[ty + i][tx] = wup[(size_t)(k0 + ty + i) * 1024 + m0 + tx];
    __syncthreads();
#pragma unroll
    for (int i = 0; i < 32; i += 8) {
        float v = tile[tx][ty + i];
        __nv_bfloat16 h = __float2bfloat16(v);
        size_t o = (size_t)(m0 + ty + i) * 1024 + k0 + tx;
        g_w2h[o] = h;
        g_w2l[o] = __float2bfloat16(v - __bfloat162float(h));
    }
}

// ---------------- prep -------------------------------------------------------
__global__ void k_prep(const float* __restrict__ aiw,
                       const float* __restrict__ aow,
                       const float* __restrict__ rkw) {
    int idx = blockIdx.x * blockDim.x + threadIdx.x;
    if (idx < BBATCH * DIM) g_xmean[idx] = 0.0f;
    if (idx < 384 * DLS) {
        int j = idx / DLS, d = idx % DLS;
        g_wt_in[d * 384 + j] = aiw[idx];
    } else if (idx < 384 * DLS + DLS * DLS) {
        int t = idx - 384 * DLS;
        g_wt_out[(t % DLS) * DLS + t / DLS] = aow[t];
    } else if (idx < 384 * DLS + 2 * DLS * DLS) {
        int t = idx - 384 * DLS - DLS * DLS;
        g_wt_rk[(t % DLS) * DLS + t / DLS] = rkw[t];
    }
}

__global__ void k_colmean(const float* __restrict__ x) {
    int b = blockIdx.y, tc = blockIdx.x, tid = threadIdx.x;
    const float* xb = x + (size_t)b * TT * DIM + (size_t)tc * 128 * DIM;
    float acc[4] = {0.f, 0.f, 0.f, 0.f};
    for (int t = 0; t < 128; t++) {
        const float* row = xb + (size_t)t * DIM + tid;
#pragma unroll
        for (int i = 0; i < 4; i++) acc[i] += row[i * 256];
    }
#pragma unroll
    for (int i = 0; i < 4; i++)
        atomicAdd(&g_xmean[b * DIM + tid + i * 256], acc[i]);
}

// ---------------- gctx + rq + k0/v0 (grid=4, block=1024) ---------------------
__global__ void __launch_bounds__(1024) k_gctx_rq2(
    const float* __restrict__ gpw, const float* __restrict__ gpb,
    const float* __restrict__ rq1w, const float* __restrict__ rq1b,
    const float* __restrict__ rqlnw, const float* __restrict__ rqlnb,
    const float* __restrict__ rq2w, const float* __restrict__ rq2b,
    const float* __restrict__ aiw, const float* __restrict__ aib) {
    __shared__ float sx[DIM];
    __shared__ float sg[DLS], st[DLS], sh[DLS];
    __shared__ float sred[8];
    int b = blockIdx.x, t = threadIdx.x;
    sx[t] = g_xmean[b * DIM + t] * (1.0f / TT);
    __syncthreads();
    int c = t >> 3, seg = t & 7;
    {
        float acc = 0.f;
        const float4* w4 = (const float4*)(gpw + (size_t)c * DIM + seg * 128);
        const float4* x4 = (const float4*)(sx + seg * 128);
#pragma unroll 8
        for (int i = 0; i < 32; i++) {
            float4 w = w4[i], xx = x4[i];
            acc += w.x * xx.x + w.y * xx.y + w.z * xx.z + w.w * xx.w;
        }
        acc += __shfl_down_sync(0xffffffffu, acc, 4, 8);
        acc += __shfl_down_sync(0xffffffffu, acc, 2, 8);
        acc += __shfl_down_sync(0xffffffffu, acc, 1, 8);
        if (seg == 0) {
            float gc = acc + gpb[c];
            sg[c] = gc;
            g_gctx[b * DLS + c] = gc;
        }
    }
    __syncthreads();
    // 128-dot helper pattern over sg
    {
        float acc = 0.f;
        const float4* w4 = (const float4*)(rq1w + (size_t)c * DLS + seg * 16);
        const float4* x4 = (const float4*)(sg + seg * 16);
#pragma unroll
        for (int i = 0; i < 4; i++) {
            float4 w = w4[i], xx = x4[i];
            acc += w.x * xx.x + w.y * xx.y + w.z * xx.z + w.w * xx.w;
        }
        acc += __shfl_down_sync(0xffffffffu, acc, 4, 8);
        acc += __shfl_down_sync(0xffffffffu, acc, 2, 8);
        acc += __shfl_down_sync(0xffffffffu, acc, 1, 8);
        if (seg == 0) st[c] = acc + rq1b[c];
    }
    // k0 = aiw rows [128..256) @ gctx
    {
        float acc = 0.f;
        const float4* w4 = (const float4*)(aiw + (size_t)(DLS + c) * DLS + seg * 16);
        const float4* x4 = (const float4*)(sg + seg * 16);
#pragma unroll
        for (int i = 0; i < 4; i++) {
            float4 w = w4[i], xx = x4[i];
            acc += w.x * xx.x + w.y * xx.y + w.z * xx.z + w.w * xx.w;
        }
        acc += __shfl_down_sync(0xffffffffu, acc, 4, 8);
        acc += __shfl_down_sync(0xffffffffu, acc, 2, 8);
        acc += __shfl_down_sync(0xffffffffu, acc, 1, 8);
        if (seg == 0) g_k0[b * DLS + c] = acc + aib[DLS + c];
    }
    // v0 = aiw rows [256..384) @ gctx
    {
        float acc = 0.f;
        const float4* w4 = (const float4*)(aiw + (size_t)(2 * DLS + c) * DLS + seg * 16);
        const float4* x4 = (const float4*)(sg + seg * 16);
#pragma unroll
        for (int i = 0; i < 4; i++) {
            float4 w = w4[i], xx = x4[i];
            acc += w.x * xx.x + w.y * xx.y + w.z * xx.z + w.w * xx.w;
        }
        acc += __shfl_down_sync(0xffffffffu, acc, 4, 8);
        acc += __shfl_down_sync(0xffffffffu, acc, 2, 8);
        acc += __shfl_down_sync(0xffffffffu, acc, 1, 8);
        if (seg == 0) g_v0[b * DLS + c] = acc + aib[2 * DLS + c];
    }
    __syncthreads();
    if (t < DLS) {
        float v = st[t];
        float s = v, q = v * v;
#pragma unroll
        for (int o = 16; o > 0; o >>= 1) {
            s += __shfl_down_sync(0xffffffffu, s, o);
            q += __shfl_down_sync(0xffffffffu, q, o);
        }
        if ((t & 31) == 0) { sred[t >> 5] = s; sred[4 + (t >> 5)] = q; }
    }
    __syncthreads();
    if (t < DLS) {
        float s = sred[0] + sred[1] + sred[2] + sred[3];
        float q = sred[4] + sred[5] + sred[6] + sred[7];
        float mu = s * (1.0f / 128.0f);
        float var = q * (1.0f / 128.0f) - mu * mu;
        float h = (st[t] - mu) * rsqrtf(var + 1e-5f) * rqlnw[t] + rqlnb[t];
        sh[t] = gelu_f(h);
    }
    __syncthreads();
    {
        float acc = 0.f;
        const float4* w4 = (const float4*)(rq2w + (size_t)c * DLS + seg * 16);
        const float4* x4 = (const float4*)(sh + seg * 16);
#pragma unroll
        for (int i = 0; i < 4; i++) {
            float4 w = w4[i], xx = x4[i];
            acc += w.x * xx.x + w.y * xx.y + w.z * xx.z + w.w * xx.w;
        }
        acc += __shfl_down_sync(0xffffffffu, acc, 4, 8);
        acc += __shfl_down_sync(0xffffffffu, acc, 2, 8);
        acc += __shfl_down_sync(0xffffffffu, acc, 1, 8);
        if (seg == 0) g_rq[b * DLS + c] = acc + rq2b[c];
    }
}

// ---------------- per-token fused attention/router (f32x2) -------------------
__global__ void __launch_bounds__(128) k_token(
    const float* __restrict__ pos, const float* __restrict__ aib,
    const float* __restrict__ aob, const float* __restrict__ nw,
    const float* __restrict__ nb, const float* __restrict__ rkb) {
    __shared__ __align__(16) float s_seqT[DLS][10];  // [d][e], e=row-1
    __shared__ float s_q[8][DLS];                    // q rows 1..8
    __shared__ float s_k[S9][DLS];
    __shared__ float s_v[S9][DLS];
    __shared__ __align__(16) float s_oT[DLS][10];
    __shared__ float s_s2[8][DLS];
    __shared__ __align__(16) float s_rfT[DLS][10];
    __shared__ float s_rq[DLS];
    __shared__ float s_mu[8], s_rs[8];
    __shared__ float s_logit[NE], s_coef[NE];

    int n = blockIdx.x, b = n >> 11, c = threadIdx.x;
    int w = c >> 5, lane = c & 31;

    float efv[8], seqv[8];
#pragma unroll
    for (int e = 0; e < 8; e++) {
        efv[e] = g_ef[(size_t)n * DIM + e * DLS + c];
        seqv[e] = efv[e] + pos[e * DLS + c];
        s_seqT[c][e] = seqv[e];
    }
    s_rq[c] = g_rq[b * DLS + c];
    s_k[0][c] = g_k0[b * DLS + c];
    s_v[0][c] = g_v0[b * DLS + c];
    __syncthreads();

    // qkv for rows 1..8: pairs of expert rows in f32x2
    {
        unsigned long long aq[4] = {}, ak[4] = {}, av[4] = {};
#pragma unroll 2
        for (int d = 0; d < DLS; d++) {
            unsigned long long w0 = bcast2(g_wt_in[d * 384 + c]);
            unsigned long long w1 = bcast2(g_wt_in[d * 384 + 128 + c]);
            unsigned long long w2 = bcast2(g_wt_in[d * 384 + 256 + c]);
            const unsigned long long* sp =
                (const unsigned long long*)&s_seqT[d][0];
#pragma unroll
            for (int p = 0; p < 4; p++) {
                unsigned long long s = sp[p];
                fma2(aq[p], s, w0);
                fma2(ak[p], s, w1);
                fma2(av[p], s, w2);
            }
        }
        float b0 = aib[c], b1 = aib[128 + c], b2 = aib[256 + c];
#pragma unroll
        for (int p = 0; p < 4; p++) {
            float lo, hi;
            unpack2(lo, hi, aq[p]);
            s_q[2 * p][c] = lo + b0;
            s_q[2 * p + 1][c] = hi + b0;
            unpack2(lo, hi, ak[p]);
            s_k[1 + 2 * p][c] = lo + b1;
            s_k[2 + 2 * p][c] = hi + b1;
            unpack2(lo, hi, av[p]);
            s_v[1 + 2 * p][c] = lo + b2;
            s_v[2 + 2 * p][c] = hi + b2;
        }
    }
    __syncthreads();

    // attention: warp = head, lanes 0..7 = q rows 1..8
    if (lane < 8) {
        int h = w;
        const float scale = 0.17677669529663688f;
        float qreg[HDV];
#pragma unroll
        for (int dd = 0; dd < HDV; dd++) qreg[dd] = s_q[lane][h * HDV + dd];
        float sc[S9];
#pragma unroll
        for (int j = 0; j < S9; j++) {
            float s = 0.f;
#pragma unroll
            for (int dd = 0; dd < HDV; dd++)
                s += qreg[dd] * s_k[j][h * HDV + dd];
            sc[j] = s * scale;
        }
        float m = sc[0];
#pragma unroll
        for (int j = 1; j < S9; j++) m = fmaxf(m, sc[j]);
        float ssum = 0.f;
#pragma unroll
        for (int j = 0; j < S9; j++) { sc[j] = expf(sc[j] - m); ssum += sc[j]; }
        float inv = 1.0f / ssum;
#pragma unroll
        for (int dd = 0; dd < HDV; dd++) {
            float o = 0.f;
#pragma unroll
            for (int j = 0; j < S9; j++) o += sc[j] * s_v[j][h * HDV + dd];
            s_oT[h * HDV + dd][lane] = o * inv;
        }
    }
    __syncthreads();

    // out proj + bias + residual (rows 1..8)
    {
        unsigned long long po[4] = {};
#pragma unroll 2
        for (int d = 0; d < DLS; d++) {
            unsigned long long wp = bcast2(g_wt_out[d * DLS + c]);
            const unsigned long long* sp = (const unsigned long long*)&s_oT[d][0];
#pragma unroll
            for (int p = 0; p < 4; p++) fma2(po[p], sp[p], wp);
        }
        float bo = aob[c];
#pragma unroll
        for (int p = 0; p < 4; p++) {
            float lo, hi;
            unpack2(lo, hi, po[p]);
            s_s2[2 * p][c] = lo + bo + seqv[2 * p];
            s_s2[2 * p + 1][c] = hi + bo + seqv[2 * p + 1];
        }
    }
    __syncthreads();

    for (int r = w; r < 8; r += 4) {
        float v0 = s_s2[r][lane], v1 = s_s2[r][lane + 32];
        float v2 = s_s2[r][lane + 64], v3 = s_s2[r][lane + 96];
        float s = v0 + v1 + v2 + v3;
        float q = v0 * v0 + v1 * v1 + v2 * v2 + v3 * v3;
#pragma unroll
        for (int o = 16; o > 0; o >>= 1) {
            s += __shfl_down_sync(0xffffffffu, s, o);
            q += __shfl_down_sync(0xffffffffu, q, o);
        }
        if (lane == 0) {
            float mu = s * (1.0f / 128.0f);
            float var = q * (1.0f / 128.0f) - mu * mu;
            s_mu[r] = mu;
            s_rs[r] = rsqrtf(var + 1e-5f);
        }
    }
    __syncthreads();
    {
        float nwc = nw[c], nbc = nb[c];
#pragma unroll
        for (int r = 0; r < 8; r++)
            s_rfT[c][r] = (s_s2[r][c] - s_mu[r]) * s_rs[r] * nwc + nbc;
    }
    __syncthreads();

    // rk + rq product
    float (*s_red)[DLS] = s_q;  // reuse
    {
        unsigned long long ra[4] = {};
#pragma unroll 2
        for (int d = 0; d < DLS; d++) {
            unsigned long long wp = bcast2(g_wt_rk[d * DLS + c]);
            const unsigned long long* sp = (const unsigned long long*)&s_rfT[d][0];
#pragma unroll
            for (int p = 0; p < 4; p++) fma2(ra[p], sp[p], wp);
        }
        float rb = rkb[c], rqc = s_rq[c];
#pragma unroll
        for (int p = 0; p < 4; p++) {
            float lo, hi;
            unpack2(lo, hi, ra[p]);
            s_red[2 * p][c] = (lo + rb) * rqc;
            s_red[2 * p + 1][c] = (hi + rb) * rqc;
        }
    }
    __syncthreads();

    for (int e = w; e < NE; e += 4) {
        float s = s_red[e][lane] + s_red[e][lane + 32] + s_red[e][lane + 64] +
                  s_red[e][lane + 96];
#pragma unroll
        for (int o = 16; o > 0; o >>= 1) s += __shfl_down_sync(0xffffffffu, s, o);
        if (lane == 0) s_logit[e] = s * 0.08838834764831845f;
    }
    __syncthreads();

    if (c == 0) {
        float p[NE];
        float m = -1e30f;
#pragma unroll
        for (int e = 0; e < NE; e++) m = fmaxf(m, s_logit[e]);
        float sum = 0.f;
#pragma unroll
        for (int e = 0; e < NE; e++) { p[e] = expf(s_logit[e] - m); sum += p[e]; }
        float inv = 1.0f / sum;
#pragma unroll
        for (int e = 0; e < NE; e++) {
            p[e] *= inv;
            g_probs[n * NE + e] = p[e];
            s_coef[e] = 0.f;
        }
        int sel[3];
        float tw[3];
        bool used[NE] = {};
#pragma unroll
        for (int t = 0; t < 3; t++) {
            int bi = 0;
            float bv = -1.f;
#pragma unroll
            for (int e = 0; e < NE; e++)
                if (!used[e] && p[e] > bv) { bv = p[e]; bi = e; }
            used[bi] = true;
            sel[t] = bi;
            tw[t] = bv;
        }
        float tinv = 1.0f / (tw[0] + tw[1] + tw[2]);
#pragma unroll
        for (int t = 0; t < 3; t++) s_coef[sel[t]] = tw[t] * tinv;
#pragma unroll
        for (int e = 0; e < NE; e++) g_coef[n * NE + e] = s_coef[e];
    }
    __syncthreads();

#pragma unroll
    for (int e = 0; e < NE; e++) {
        size_t idx = (size_t)n * DIM + e * DLS + c;
        float a = s_coef[e] * gelu_f(efv[e]);
        __nv_bfloat16 h = __float2bfloat16(a);
        g_ah[idx] = h;
        g_al[idx] = __float2bfloat16(a - __bfloat162float(h));
    }
}

// ---------------- aux loss ---------------------------------------------------
__global__ void k_aux(float* __restrict__ out) {
    __shared__ float sp[256 * 8];
    __shared__ float sc2[256 * 8];
    int tid = threadIdx.x;
    float ps[NE], cs[NE];
#pragma unroll
    for (int e = 0; e < NE; e++) { ps[e] = 0.f; cs[e] = 0.f; }
    for (int nn = tid; nn < NTOK; nn += 256) {
#pragma unroll
        for (int e = 0; e < NE; e++) {
            ps[e] += g_probs[nn * NE + e];
            cs[e] += (g_coef[nn * NE + e] > 0.f) ? 1.0f : 0.0f;
        }
    }
#pragma unroll
    for (int e = 0; e < NE; e++) {
        sp[e * 256 + tid] = ps[e];
        sc2[e * 256 + tid] = cs[e];
    }
    __syncthreads();
    if (tid < NE) {
        float a = 0.f, bsum = 0.f;
        for (int i = 0; i < 256; i++) {
            a += sp[tid * 256 + i];
            bsum += sc2[tid * 256 + i];
        }
        sp[tid] = a;
        sc2[tid] = bsum;
    }
    __syncthreads();
    if (tid == 0) {
        float aux = 0.f;
        for (int e = 0; e < NE; e++)
            aux += (sp[e] * (1.0f / NTOK)) * (sc2[e] * (1.0f / NTOK));
        out[(size_t)NTOK * DIM] = 8.0f * aux;
    }
}

// ---------------- launch -----------------------------------------------------
extern "C" void kernel_launch(void* const* d_in, const int* in_sizes, int n_in,
                              void* d_out, int out_size) {
    const float* x    = (const float*)d_in[0];
    const float* wdn  = (const float*)d_in[1];
    const float* pos  = (const float*)d_in[2];
    const float* gpw  = (const float*)d_in[3];
    const float* gpb  = (const float*)d_in[4];
    const float* aiw  = (const float*)d_in[5];
    const float* aib  = (const float*)d_in[6];
    const float* aow  = (const float*)d_in[7];
    const float* aob  = (const float*)d_in[8];
    const float* nw   = (const float*)d_in[9];
    const float* nb   = (const float*)d_in[10];
    const float* rq1w = (const float*)d_in[11];
    const float* rq1b = (const float*)d_in[12];
    const float* rqlnw= (const float*)d_in[13];
    const float* rqlnb= (const float*)d_in[14];
    const float* rq2w = (const float*)d_in[15];
    const float* rq2b = (const float*)d_in[16];
    const float* rkw  = (const float*)d_in[17];
    const float* rkb  = (const float*)d_in[18];
    const float* wup  = (const float*)d_in[19];
    float* out = (float*)d_out;

    const int SMEM = 3 * 32768;  // 3 stages x (A 16KB + B 16KB)
    cudaFuncSetAttribute(k_gemm1, cudaFuncAttributeMaxDynamicSharedMemorySize, SMEM);
    cudaFuncSetAttribute(k_gemm2, cudaFuncAttributeMaxDynamicSharedMemorySize, SMEM);

    k_prep<<<320, 256>>>(aiw, aow, rkw);
    k_split3_x<<<8192, 256>>>(x);
    k_split3_w<<<1024, 256>>>(wdn);
    k_tsplit2_wup<<<dim3(32, 32), dim3(32, 8)>>>(wup);
    k_colmean<<<dim3(16, BBATCH), 256>>>(x);
    k_gemm1<<<dim3(8, 64), 256, SMEM>>>();
    k_gctx_rq2<<<BBATCH, 1024>>>(gpw, gpb, rq1w, rq1b, rqlnw, rqlnb, rq2w, rq2b,
                                 aiw, aib);
    k_token<<<NTOK, 128>>>(pos, aib, aob, nw, nb, rkb);
    k_gemm2<<<dim3(8, 64), 256, SMEM>>>(out);
    k_aux<<<1, 256>>>(out);
}

// round 11
// speedup vs baseline: 1.3215x; 1.3215x over previous
#include <cuda_runtime.h>
#include <cuda_fp16.h>
#include <math.h>

#define NTOK 8192
#define DIM  1024
#define DLS  128
#define NE   8
#define HDV  32
#define TT   2048
#define BBATCH 4
#define S9   9
#define INV512 (1.0f / 512.0f)

// ---------------- scratch ----------------------------------------------------
__device__ float g_ef[NTOK * DIM];
__device__ float g_qkv[NTOK * NE * 384];
__device__ float g_xmean[BBATCH * DIM];
__device__ float g_gctx[BBATCH * DLS];
__device__ float g_rq[BBATCH * DLS];
__device__ float g_k0[BBATCH * DLS];
__device__ float g_v0[BBATCH * DLS];
__device__ float g_probs[NTOK * NE];
__device__ float g_coef[NTOK * NE];
__device__ float g_wt_out[DLS * DLS];
__device__ float g_wt_rk[DLS * DLS];

__device__ __align__(16) __half g_xh[NTOK * DIM];
__device__ __align__(16) __half g_xl[NTOK * DIM];
__device__ __align__(16) __half g_w1h[DIM * DIM];   // w_down * 512
__device__ __align__(16) __half g_w1l[DIM * DIM];
__device__ __align__(16) __half g_sh[NTOK * DIM];   // seq = ef + pos (8N x 128)
__device__ __align__(16) __half g_sl[NTOK * DIM];
__device__ __align__(16) __half g_aih[384 * DLS];   // attn_in_w * 512
__device__ __align__(16) __half g_ail[384 * DLS];
__device__ __align__(16) __half g_ah[NTOK * DIM];   // coef*gelu(ef)
__device__ __align__(16) __half g_al[NTOK * DIM];
__device__ __align__(16) __half g_w2h[DIM * DIM];   // w_up^T * 512
__device__ __align__(16) __half g_w2l[DIM * DIM];

__device__ __forceinline__ float gelu_f(float x) {
    return 0.5f * x * (1.0f + erff(x * 0.70710678118654752440f));
}

// ---------------- PTX helpers ------------------------------------------------
__device__ __forceinline__ unsigned smem_u32(const void* p) {
    unsigned a;
    asm("{ .reg .u64 t; cvta.to.shared.u64 t, %1; cvt.u32.u64 %0, t; }"
        : "=r"(a) : "l"(p));
    return a;
}
__device__ __forceinline__ void cp16(unsigned d, const void* g) {
    asm volatile("cp.async.cg.shared.global [%0], [%1], 16;" :: "r"(d), "l"(g));
}
__device__ __forceinline__ void ldm_x4(unsigned* r, unsigned addr) {
    asm volatile("ldmatrix.sync.aligned.m8n8.x4.shared.b16 {%0,%1,%2,%3}, [%4];"
                 : "=r"(r[0]), "=r"(r[1]), "=r"(r[2]), "=r"(r[3]) : "r"(addr));
}
__device__ __forceinline__ void mma16816(float* d, const unsigned* a,
                                         unsigned b0, unsigned b1) {
    asm volatile(
        "mma.sync.aligned.m16n8k16.row.col.f32.f16.f16.f32 "
        "{%0,%1,%2,%3}, {%4,%5,%6,%7}, {%8,%9}, {%0,%1,%2,%3};"
        : "+f"(d[0]), "+f"(d[1]), "+f"(d[2]), "+f"(d[3])
        : "r"(a[0]), "r"(a[1]), "r"(a[2]), "r"(a[3]), "r"(b0), "r"(b1));
}
__device__ __forceinline__ void fma2(unsigned long long& d, unsigned long long a,
                                     unsigned long long b) {
    asm("fma.rn.f32x2 %0, %1, %2, %0;" : "+l"(d) : "l"(a), "l"(b));
}
__device__ __forceinline__ unsigned long long bcast2(float x) {
    unsigned long long r;
    asm("mov.b64 %0, {%1, %1};" : "=l"(r) : "f"(x));
    return r;
}
__device__ __forceinline__ void unpack2(float& lo, float& hi,
                                        unsigned long long v) {
    asm("mov.b64 {%0, %1}, %2;" : "=f"(lo), "=f"(hi) : "l"(v));
}

// ---------------- generic HMMA GEMM core -------------------------------------
// 128x128 C tile = sum_p A_p . B_p^T, K = KCH*64 per product, fp16 row stride
// STRIDE. 8 warps (2Mx4N), 3-stage cp.async pipeline, drained tail.
template <int NP, int KCH, int STRIDE, typename E>
__device__ __forceinline__ void gemm_run(const __half* const* Al,
                                         const __half* const* Bl,
                                         const signed char* pi,
                                         const signed char* pj, E epi) {
    extern __shared__ __align__(128) char smem[];
    int tid = threadIdx.x, lane = tid & 31, warp = tid >> 5;
    int n0 = blockIdx.x * 128, m0 = blockIdx.y * 128;
    int wm = (warp & 1) * 64, wn = (warp >> 1) * 32;
    unsigned sbase = smem_u32(smem);
    float acc[4][4][4] = {};

    auto load = [&](int t, int s) {
        const __half* A = Al[pi[t / KCH]];
        const __half* B = Bl[pj[t / KCH]];
        int k0 = (t % KCH) * 64;
        unsigned sa = sbase + (unsigned)s * 32768u, sb = sa + 16384u;
#pragma unroll
        for (int i = 0; i < 4; i++) {
            int cid = tid + (i << 8);
            int r = cid >> 3, c = cid & 7;
            unsigned off = (unsigned)(r * 128 + ((c ^ (r & 7)) << 4));
            cp16(sa + off, (const char*)(A + (size_t)(m0 + r) * STRIDE + k0) + c * 16);
            cp16(sb + off, (const char*)(B + (size_t)(n0 + r) * STRIDE + k0) + c * 16);
        }
        asm volatile("cp.async.commit_group;" ::: "memory");
    };

    constexpr int T = NP * KCH;
    load(0, 0);
    load(1, 1);
#pragma unroll 1
    for (int t = 0; t < T; t++) {
        if (t + 1 < T) {
            asm volatile("cp.async.wait_group 1;" ::: "memory");
        } else {
            asm volatile("cp.async.wait_group 0;" ::: "memory");  // drain tail
        }
        __syncthreads();
        if (t + 2 < T) load(t + 2, (t + 2) % 3);
        unsigned sa = sbase + (unsigned)(t % 3) * 32768u, sb = sa + 16384u;
#pragma unroll
        for (int ks = 0; ks < 4; ks++) {
            int clo = ks * 2;
            unsigned a[4][4], b[2][4];
#pragma unroll
            for (int g = 0; g < 4; g++) {
                int row = wm + g * 16 + (lane & 15);
                int c = clo + (lane >> 4);
                ldm_x4(a[g], sa + row * 128 + ((c ^ (row & 7)) << 4));
            }
#pragma unroll
            for (int h = 0; h < 2; h++) {
                int row = wn + h * 16 + ((lane >> 4) << 3) + (lane & 7);
                int c = clo + ((lane >> 3) & 1);
                ldm_x4(b[h], sb + row * 128 + ((c ^ (row & 7)) << 4));
            }
#pragma unroll
            for (int i = 0; i < 4; i++)
#pragma unroll
                for (int j = 0; j < 4; j++) {
                    const unsigned* bf = &b[j >> 1][(j & 1) * 2];
                    mma16816(acc[i][j], a[i], bf[0], bf[1]);
                }
        }
        __syncthreads();
    }
#pragma unroll
    for (int i = 0; i < 4; i++) {
        int row = m0 + wm + i * 16 + (lane >> 2);
#pragma unroll
        for (int j = 0; j < 4; j++)
            epi(row, n0 + wn + j * 8 + (lane & 3) * 2, acc[i][j]);
    }
}

__device__ __forceinline__ __half2 mk_h(float a, float b) {
    return __halves2half2(__float2half(a), __float2half(b));
}
__device__ __forceinline__ __half2 mk_l(float a, __half ha, float b, __half hb) {
    return __halves2half2(__float2half(a - __half2float(ha)),
                          __float2half(b - __half2float(hb)));
}

static const __device__ signed char PI3[3] = {0, 0, 1};
static const __device__ signed char PJ3[3] = {0, 1, 0};

// GEMM1: ef = x @ w_down^T; also emit fp16 split of (ef + pos)
__global__ void __launch_bounds__(256) k_gemm1(const float* __restrict__ pos) {
    const __half* A[2] = {g_xh, g_xl};
    const __half* B[2] = {g_w1h, g_w1l};
    gemm_run<3, 16, 1024>(A, B, PI3, PJ3, [&](int row, int col, const float* a) {
#pragma unroll
        for (int hh = 0; hh < 2; hh++) {
            int r = row + hh * 8;
            float v0 = a[hh * 2] * INV512, v1 = a[hh * 2 + 1] * INV512;
            size_t o = (size_t)r * 1024 + col;
            *(float2*)(g_ef + o) = make_float2(v0, v1);
            float2 pv = *(const float2*)(pos + col);
            float s0 = v0 + pv.x, s1 = v1 + pv.y;
            __half2 h = mk_h(s0, s1);
            *(__half2*)(g_sh + o) = h;
            *(__half2*)(g_sl + o) = mk_l(s0, __low2half(h), s1, __high2half(h));
        }
    });
}

// qkv GEMM: (8N,128) seq @ attn_in_w^T -> (8N,384) + bias
__global__ void __launch_bounds__(256) k_qkvg(const float* __restrict__ aib) {
    const __half* A[2] = {g_sh, g_sl};
    const __half* B[2] = {g_aih, g_ail};
    gemm_run<3, 2, 128>(A, B, PI3, PJ3, [&](int row, int col, const float* a) {
        float2 bv = *(const float2*)(aib + col);
#pragma unroll
        for (int hh = 0; hh < 2; hh++) {
            int r = row + hh * 8;
            *(float2*)(g_qkv + (size_t)r * 384 + col) =
                make_float2(a[hh * 2] * INV512 + bv.x,
                            a[hh * 2 + 1] * INV512 + bv.y);
        }
    });
}

// GEMM2: out = Ahat @ w_up
__global__ void __launch_bounds__(256) k_gemm2(float* __restrict__ C) {
    const __half* A[2] = {g_ah, g_al};
    const __half* B[2] = {g_w2h, g_w2l};
    gemm_run<3, 16, 1024>(A, B, PI3, PJ3, [&](int row, int col, const float* a) {
#pragma unroll
        for (int hh = 0; hh < 2; hh++)
            *(float2*)(C + (size_t)(row + hh * 8) * 1024 + col) =
                make_float2(a[hh * 2] * INV512, a[hh * 2 + 1] * INV512);
    });
}

// ---------------- split kernels (device globals referenced IN device code) ---
__device__ __forceinline__ void split2_core(float4 v, float scale,
                                            __half* dh, __half* dl, size_t i) {
    float vs[4] = {v.x * scale, v.y * scale, v.z * scale, v.w * scale};
    __half2 h0 = mk_h(vs[0], vs[1]), h1 = mk_h(vs[2], vs[3]);
    ((__half2*)dh)[2 * i] = h0;
    ((__half2*)dh)[2 * i + 1] = h1;
    ((__half2*)dl)[2 * i] = mk_l(vs[0], __low2half(h0), vs[1], __high2half(h0));
    ((__half2*)dl)[2 * i + 1] = mk_l(vs[2], __low2half(h1), vs[3], __high2half(h1));
}
__global__ void k_split2_x(const float* __restrict__ x) {
    size_t i = (size_t)blockIdx.x * blockDim.x + threadIdx.x;
    split2_core(((const float4*)x)[i], 1.0f, g_xh, g_xl, i);
}
__global__ void k_split2_w1(const float* __restrict__ w) {
    size_t i = (size_t)blockIdx.x * blockDim.x + threadIdx.x;
    split2_core(((const float4*)w)[i], 512.0f, g_w1h, g_w1l, i);
}
__global__ void k_tsplit2_wup(const float* __restrict__ wup) {
    __shared__ float tile[32][33];
    int k0 = blockIdx.y * 32, m0 = blockIdx.x * 32;
    int tx = threadIdx.x, ty = threadIdx.y;
#pragma unroll
    for (int i = 0; i < 32; i += 8)
        tile[ty + i][tx] = wup[(size_t)(k0 + ty + i) * 1024 + m0 + tx];
    __syncthreads();
#pragma unroll
    for (int i = 0; i < 32; i += 8) {
        float v = tile[tx][ty + i] * 512.0f;
        __half h = __float2half(v);
        size_t o = (size_t)(m0 + ty + i) * 1024 + k0 + tx;
        g_w2h[o] = h;
        g_w2l[o] = __float2half(v - __half2float(h));
    }
}

// ---------------- prep -------------------------------------------------------
__global__ void k_prep(const float* __restrict__ aow,
                       const float* __restrict__ rkw,
                       const float* __restrict__ aiw) {
    int idx = blockIdx.x * blockDim.x + threadIdx.x;
    if (idx < BBATCH * DIM) g_xmean[idx] = 0.0f;
    if (idx < DLS * DLS) {
        g_wt_out[(idx % DLS) * DLS + idx / DLS] = aow[idx];
        g_wt_rk[(idx % DLS) * DLS + idx / DLS] = rkw[idx];
    }
    if (idx < 384 * DLS) {
        float v = aiw[idx] * 512.0f;
        __half h = __float2half(v);
        g_aih[idx] = h;
        g_ail[idx] = __float2half(v - __half2float(h));
    }
}

__global__ void k_colmean(const float* __restrict__ x) {
    int b = blockIdx.y, tc = blockIdx.x, tid = threadIdx.x;
    const float* xb = x + (size_t)b * TT * DIM + (size_t)tc * 128 * DIM;
    float acc[4] = {0.f, 0.f, 0.f, 0.f};
    for (int t = 0; t < 128; t++) {
        const float* row = xb + (size_t)t * DIM + tid;
#pragma unroll
        for (int i = 0; i < 4; i++) acc[i] += row[i * 256];
    }
#pragma unroll
    for (int i = 0; i < 4; i++)
        atomicAdd(&g_xmean[b * DIM + tid + i * 256], acc[i]);
}

// ---------------- gctx + rq + k0/v0 ------------------------------------------
__global__ void __launch_bounds__(1024) k_gctx_rq2(
    const float* __restrict__ gpw, const float* __restrict__ gpb,
    const float* __restrict__ rq1w, const float* __restrict__ rq1b,
    const float* __restrict__ rqlnw, const float* __restrict__ rqlnb,
    const float* __restrict__ rq2w, const float* __restrict__ rq2b,
    const float* __restrict__ aiw, const float* __restrict__ aib) {
    __shared__ float sx[DIM];
    __shared__ float sg[DLS], st[DLS], sh[DLS];
    __shared__ float sred[8];
    int b = blockIdx.x, t = threadIdx.x;
    sx[t] = g_xmean[b * DIM + t] * (1.0f / TT);
    __syncthreads();
    int c = t >> 3, seg = t & 7;
    {
        float acc = 0.f;
        const float4* w4 = (const float4*)(gpw + (size_t)c * DIM + seg * 128);
        const float4* x4 = (const float4*)(sx + seg * 128);
#pragma unroll 8
        for (int i = 0; i < 32; i++) {
            float4 w = w4[i], xx = x4[i];
            acc += w.x * xx.x + w.y * xx.y + w.z * xx.z + w.w * xx.w;
        }
        acc += __shfl_down_sync(0xffffffffu, acc, 4, 8);
        acc += __shfl_down_sync(0xffffffffu, acc, 2, 8);
        acc += __shfl_down_sync(0xffffffffu, acc, 1, 8);
        if (seg == 0) {
            float gc = acc + gpb[c];
            sg[c] = gc;
            g_gctx[b * DLS + c] = gc;
        }
    }
    __syncthreads();
    {
        float acc = 0.f;
        const float4* w4 = (const float4*)(rq1w + (size_t)c * DLS + seg * 16);
        const float4* x4 = (const float4*)(sg + seg * 16);
#pragma unroll
        for (int i = 0; i < 4; i++) {
            float4 w = w4[i], xx = x4[i];
            acc += w.x * xx.x + w.y * xx.y + w.z * xx.z + w.w * xx.w;
        }
        acc += __shfl_down_sync(0xffffffffu, acc, 4, 8);
        acc += __shfl_down_sync(0xffffffffu, acc, 2, 8);
        acc += __shfl_down_sync(0xffffffffu, acc, 1, 8);
        if (seg == 0) st[c] = acc + rq1b[c];
    }
    {
        float acc = 0.f;
        const float4* w4 = (const float4*)(aiw + (size_t)(DLS + c) * DLS + seg * 16);
        const float4* x4 = (const float4*)(sg + seg * 16);
#pragma unroll
        for (int i = 0; i < 4; i++) {
            float4 w = w4[i], xx = x4[i];
            acc += w.x * xx.x + w.y * xx.y + w.z * xx.z + w.w * xx.w;
        }
        acc += __shfl_down_sync(0xffffffffu, acc, 4, 8);
        acc += __shfl_down_sync(0xffffffffu, acc, 2, 8);
        acc += __shfl_down_sync(0xffffffffu, acc, 1, 8);
        if (seg == 0) g_k0[b * DLS + c] = acc + aib[DLS + c];
    }
    {
        float acc = 0.f;
        const float4* w4 = (const float4*)(aiw + (size_t)(2 * DLS + c) * DLS + seg * 16);
        const float4* x4 = (const float4*)(sg + seg * 16);
#pragma unroll
        for (int i = 0; i < 4; i++) {
            float4 w = w4[i], xx = x4[i];
            acc += w.x * xx.x + w.y * xx.y + w.z * xx.z + w.w * xx.w;
        }
        acc += __shfl_down_sync(0xffffffffu, acc, 4, 8);
        acc += __shfl_down_sync(0xffffffffu, acc, 2, 8);
        acc += __shfl_down_sync(0xffffffffu, acc, 1, 8);
        if (seg == 0) g_v0[b * DLS + c] = acc + aib[2 * DLS + c];
    }
    __syncthreads();
    if (t < DLS) {
        float v = st[t];
        float s = v, q = v * v;
#pragma unroll
        for (int o = 16; o > 0; o >>= 1) {
            s += __shfl_down_sync(0xffffffffu, s, o);
            q += __shfl_down_sync(0xffffffffu, q, o);
        }
        if ((t & 31) == 0) { sred[t >> 5] = s; sred[4 + (t >> 5)] = q; }
    }
    __syncthreads();
    if (t < DLS) {
        float s = sred[0] + sred[1] + sred[2] + sred[3];
        float q = sred[4] + sred[5] + sred[6] + sred[7];
        float mu = s * (1.0f / 128.0f);
        float var = q * (1.0f / 128.0f) - mu * mu;
        float h = (st[t] - mu) * rsqrtf(var + 1e-5f) * rqlnw[t] + rqlnb[t];
        sh[t] = gelu_f(h);
    }
    __syncthreads();
    {
        float acc = 0.f;
        const float4* w4 = (const float4*)(rq2w + (size_t)c * DLS + seg * 16);
        const float4* x4 = (const float4*)(sh + seg * 16);
#pragma unroll
        for (int i = 0; i < 4; i++) {
            float4 w = w4[i], xx = x4[i];
            acc += w.x * xx.x + w.y * xx.y + w.z * xx.z + w.w * xx.w;
        }
        acc += __shfl_down_sync(0xffffffffu, acc, 4, 8);
        acc += __shfl_down_sync(0xffffffffu, acc, 2, 8);
        acc += __shfl_down_sync(0xffffffffu, acc, 1, 8);
        if (seg == 0) g_rq[b * DLS + c] = acc + rq2b[c];
    }
}

// ---------------- per-token: attention + router ------------------------------
__global__ void __launch_bounds__(128) k_attn(
    const float* __restrict__ pos, const float* __restrict__ aob,
    const float* __restrict__ nw, const float* __restrict__ nb,
    const float* __restrict__ rkb) {
    __shared__ float s_q[8][129];
    __shared__ float s_k[S9][DLS];
    __shared__ float s_v[S9][DLS];
    __shared__ __align__(16) float s_oT[DLS][10];
    __shared__ float s_s2[8][DLS];
    __shared__ __align__(16) float s_rfT[DLS][10];
    __shared__ float s_rq[DLS];
    __shared__ float s_mu[8], s_rs[8];
    __shared__ float s_logit[NE], s_coef[NE];

    int n = blockIdx.x, b = n >> 11, c = threadIdx.x;
    int w = c >> 5, lane = c & 31;

    float efv[8];
#pragma unroll
    for (int e = 0; e < 8; e++) efv[e] = g_ef[(size_t)n * DIM + e * DLS + c];
    const float* qb = g_qkv + (size_t)n * 8 * 384;
#pragma unroll
    for (int e = 0; e < 8; e++) {
        s_q[e][c] = qb[e * 384 + c];
        s_k[1 + e][c] = qb[e * 384 + 128 + c];
        s_v[1 + e][c] = qb[e * 384 + 256 + c];
    }
    s_k[0][c] = g_k0[b * DLS + c];
    s_v[0][c] = g_v0[b * DLS + c];
    s_rq[c] = g_rq[b * DLS + c];
    __syncthreads();

    if (lane < 8) {
        int h = w;
        const float scale = 0.17677669529663688f;
        float qreg[HDV];
#pragma unroll
        for (int dd = 0; dd < HDV; dd++) qreg[dd] = s_q[lane][h * HDV + dd];
        float sc[S9];
#pragma unroll
        for (int j = 0; j < S9; j++) {
            float s = 0.f;
#pragma unroll
            for (int dd = 0; dd < HDV; dd++) s += qreg[dd] * s_k[j][h * HDV + dd];
            sc[j] = s * scale;
        }
        float m = sc[0];
#pragma unroll
        for (int j = 1; j < S9; j++) m = fmaxf(m, sc[j]);
        float ssum = 0.f;
#pragma unroll
        for (int j = 0; j < S9; j++) { sc[j] = expf(sc[j] - m); ssum += sc[j]; }
        float inv = 1.0f / ssum;
#pragma unroll
        for (int dd = 0; dd < HDV; dd++) {
            float o = 0.f;
#pragma unroll
            for (int j = 0; j < S9; j++) o += sc[j] * s_v[j][h * HDV + dd];
            s_oT[h * HDV + dd][lane] = o * inv;
        }
    }
    __syncthreads();

    float seqv[8];
#pragma unroll
    for (int e = 0; e < 8; e++) seqv[e] = efv[e] + pos[e * DLS + c];
    {
        unsigned long long po[4] = {};
#pragma unroll 2
        for (int d = 0; d < DLS; d++) {
            unsigned long long wp = bcast2(g_wt_out[d * DLS + c]);
            const unsigned long long* sp = (const unsigned long long*)&s_oT[d][0];
#pragma unroll
            for (int p = 0; p < 4; p++) fma2(po[p], sp[p], wp);
        }
        float bo = aob[c];
#pragma unroll
        for (int p = 0; p < 4; p++) {
            float lo, hi;
            unpack2(lo, hi, po[p]);
            s_s2[2 * p][c] = lo + bo + seqv[2 * p];
            s_s2[2 * p + 1][c] = hi + bo + seqv[2 * p + 1];
        }
    }
    __syncthreads();

    for (int r = w; r < 8; r += 4) {
        float v0 = s_s2[r][lane], v1 = s_s2[r][lane + 32];
        float v2 = s_s2[r][lane + 64], v3 = s_s2[r][lane + 96];
        float s = v0 + v1 + v2 + v3;
        float q = v0 * v0 + v1 * v1 + v2 * v2 + v3 * v3;
#pragma unroll
        for (int o = 16; o > 0; o >>= 1) {
            s += __shfl_down_sync(0xffffffffu, s, o);
            q += __shfl_down_sync(0xffffffffu, q, o);
        }
        if (lane == 0) {
            float mu = s * (1.0f / 128.0f);
            float var = q * (1.0f / 128.0f) - mu * mu;
            s_mu[r] = mu;
            s_rs[r] = rsqrtf(var + 1e-5f);
        }
    }
    __syncthreads();
    {
        float nwc = nw[c], nbc = nb[c];
#pragma unroll
        for (int r = 0; r < 8; r++)
            s_rfT[c][r] = (s_s2[r][c] - s_mu[r]) * s_rs[r] * nwc + nbc;
    }
    __syncthreads();

    float (*s_red)[129] = s_q;
    {
        unsigned long long ra[4] = {};
#pragma unroll 2
        for (int d = 0; d < DLS; d++) {
            unsigned long long wp = bcast2(g_wt_rk[d * DLS + c]);
            const unsigned long long* sp = (const unsigned long long*)&s_rfT[d][0];
#pragma unroll
            for (int p = 0; p < 4; p++) fma2(ra[p], sp[p], wp);
        }
        float rb = rkb[c], rqc = s_rq[c];
#pragma unroll
        for (int p = 0; p < 4; p++) {
            float lo, hi;
            unpack2(lo, hi, ra[p]);
            s_red[2 * p][c] = (lo + rb) * rqc;
            s_red[2 * p + 1][c] = (hi + rb) * rqc;
        }
    }
    __syncthreads();

    for (int e = w; e < NE; e += 4) {
        float s = s_red[e][lane] + s_red[e][lane + 32] + s_red[e][lane + 64] +
                  s_red[e][lane + 96];
#pragma unroll
        for (int o = 16; o > 0; o >>= 1) s += __shfl_down_sync(0xffffffffu, s, o);
        if (lane == 0) s_logit[e] = s * 0.08838834764831845f;
    }
    __syncthreads();

    if (c == 0) {
        float p[NE];
        float m = -1e30f;
#pragma unroll
        for (int e = 0; e < NE; e++) m = fmaxf(m, s_logit[e]);
        float sum = 0.f;
#pragma unroll
        for (int e = 0; e < NE; e++) { p[e] = expf(s_logit[e] - m); sum += p[e]; }
        float inv = 1.0f / sum;
#pragma unroll
        for (int e = 0; e < NE; e++) {
            p[e] *= inv;
            g_probs[n * NE + e] = p[e];
            s_coef[e] = 0.f;
        }
        int sel[3];
        float tw[3];
        bool used[NE] = {};
#pragma unroll
        for (int t = 0; t < 3; t++) {
            int bi = 0;
            float bv = -1.f;
#pragma unroll
            for (int e = 0; e < NE; e++)
                if (!used[e] && p[e] > bv) { bv = p[e]; bi = e; }
            used[bi] = true;
            sel[t] = bi;
            tw[t] = bv;
        }
        float tinv = 1.0f / (tw[0] + tw[1] + tw[2]);
#pragma unroll
        for (int t = 0; t < 3; t++) s_coef[sel[t]] = tw[t] * tinv;
#pragma unroll
        for (int e = 0; e < NE; e++) g_coef[n * NE + e] = s_coef[e];
    }
    __syncthreads();

#pragma unroll
    for (int e = 0; e < NE; e++) {
        size_t idx = (size_t)n * DIM + e * DLS + c;
        float a = s_coef[e] * gelu_f(efv[e]);
        __half h = __float2half(a);
        g_ah[idx] = h;
        g_al[idx] = __float2half(a - __half2float(h));
    }
}

// ---------------- aux loss ---------------------------------------------------
__global__ void k_aux(float* __restrict__ out) {
    __shared__ float sp[256 * 8];
    __shared__ float sc2[256 * 8];
    int tid = threadIdx.x;
    float ps[NE], cs[NE];
#pragma unroll
    for (int e = 0; e < NE; e++) { ps[e] = 0.f; cs[e] = 0.f; }
    for (int nn = tid; nn < NTOK; nn += 256) {
#pragma unroll
        for (int e = 0; e < NE; e++) {
            ps[e] += g_probs[nn * NE + e];
            cs[e] += (g_coef[nn * NE + e] > 0.f) ? 1.0f : 0.0f;
        }
    }
#pragma unroll
    for (int e = 0; e < NE; e++) {
        sp[e * 256 + tid] = ps[e];
        sc2[e * 256 + tid] = cs[e];
    }
    __syncthreads();
    if (tid < NE) {
        float a = 0.f, bsum = 0.f;
        for (int i = 0; i < 256; i++) {
            a += sp[tid * 256 + i];
            bsum += sc2[tid * 256 + i];
        }
        sp[tid] = a;
        sc2[tid] = bsum;
    }
    __syncthreads();
    if (tid == 0) {
        float aux = 0.f;
        for (int e = 0; e < NE; e++)
            aux += (sp[e] * (1.0f / NTOK)) * (sc2[e] * (1.0f / NTOK));
        out[(size_t)NTOK * DIM] = 8.0f * aux;
    }
}

// ---------------- launch -----------------------------------------------------
extern "C" void kernel_launch(void* const* d_in, const int* in_sizes, int n_in,
                              void* d_out, int out_size) {
    const float* x    = (const float*)d_in[0];
    const float* wdn  = (const float*)d_in[1];
    const float* pos  = (const float*)d_in[2];
    const float* gpw  = (const float*)d_in[3];
    const float* gpb  = (const float*)d_in[4];
    const float* aiw  = (const float*)d_in[5];
    const float* aib  = (const float*)d_in[6];
    const float* aow  = (const float*)d_in[7];
    const float* aob  = (const float*)d_in[8];
    const float* nw   = (const float*)d_in[9];
    const float* nb   = (const float*)d_in[10];
    const float* rq1w = (const float*)d_in[11];
    const float* rq1b = (const float*)d_in[12];
    const float* rqlnw= (const float*)d_in[13];
    const float* rqlnb= (const float*)d_in[14];
    const float* rq2w = (const float*)d_in[15];
    const float* rq2b = (const float*)d_in[16];
    const float* rkw  = (const float*)d_in[17];
    const float* rkb  = (const float*)d_in[18];
    const float* wup  = (const float*)d_in[19];
    float* out = (float*)d_out;

    const int SMEM = 3 * 32768;
    cudaFuncSetAttribute(k_gemm1, cudaFuncAttributeMaxDynamicSharedMemorySize, SMEM);
    cudaFuncSetAttribute(k_qkvg, cudaFuncAttributeMaxDynamicSharedMemorySize, SMEM);
    cudaFuncSetAttribute(k_gemm2, cudaFuncAttributeMaxDynamicSharedMemorySize, SMEM);

    k_prep<<<192, 256>>>(aow, rkw, aiw);
    k_split2_x<<<8192, 256>>>(x);
    k_split2_w1<<<1024, 256>>>(wdn);
    k_tsplit2_wup<<<dim3(32, 32), dim3(32, 8)>>>(wup);
    k_colmean<<<dim3(16, BBATCH), 256>>>(x);
    k_gctx_rq2<<<BBATCH, 1024>>>(gpw, gpb, rq1w, rq1b, rqlnw, rqlnb, rq2w, rq2b,
                                 aiw, aib);
    k_gemm1<<<dim3(8, 64), 256, SMEM>>>(pos);
    k_qkvg<<<dim3(3, 512), 256, SMEM>>>(aib);
    k_attn<<<NTOK, 128>>>(pos, aob, nw, nb, rkb);
    k_gemm2<<<dim3(8, 64), 256, SMEM>>>(out);
    k_aux<<<1, 256>>>(out);
}

// round 13
// speedup vs baseline: 1.5992x; 1.2101x over previous
#include <cuda_runtime.h>
#include <cuda_fp16.h>
#include <math.h>

#define NTOK 8192
#define DIM  1024
#define DLS  128
#define NE   8
#define HDV  32
#define TT   2048
#define BBATCH 4
#define S9   9
#define INV512 (1.0f / 512.0f)

// ---------------- scratch ----------------------------------------------------
__device__ float g_ef[NTOK * DIM];
__device__ float g_qkv[NTOK * NE * 384];
__device__ float g_xmean[BBATCH * DIM];
__device__ float g_gctx[BBATCH * DLS];
__device__ float g_k0[BBATCH * DLS];
__device__ float g_v0[BBATCH * DLS];
__device__ float g_vv[BBATCH * DLS];   // v = nw ⊙ (rq @ rk_w)
__device__ float g_sc[BBATCH * 2];     // alpha, gamma
__device__ float g_probs[NTOK * NE];
__device__ float g_coef[NTOK * NE];
__device__ float g_wt_out[DLS * DLS];
__device__ float g_wt_rk[DLS * DLS];   // [d][c] = rk_w[c][d]

__device__ __align__(16) __half g_xh[NTOK * DIM];
__device__ __align__(16) __half g_xl[NTOK * DIM];
__device__ __align__(16) __half g_w1h[DIM * DIM];   // w_down * 512
__device__ __align__(16) __half g_w1l[DIM * DIM];
__device__ __align__(16) __half g_sh[NTOK * DIM];   // seq = ef + pos (8N x 128)
__device__ __align__(16) __half g_sl[NTOK * DIM];
__device__ __align__(16) __half g_aih[384 * DLS];   // attn_in_w * 512
__device__ __align__(16) __half g_ail[384 * DLS];
__device__ __align__(16) __half g_ah[NTOK * DIM];   // coef*gelu(ef)
__device__ __align__(16) __half g_al[NTOK * DIM];
__device__ __align__(16) __half g_w2h[DIM * DIM];   // w_up^T * 512
__device__ __align__(16) __half g_w2l[DIM * DIM];

__device__ __forceinline__ float gelu_f(float x) {
    return 0.5f * x * (1.0f + erff(x * 0.70710678118654752440f));
}

// ---------------- PTX helpers ------------------------------------------------
__device__ __forceinline__ unsigned smem_u32(const void* p) {
    unsigned a;
    asm("{ .reg .u64 t; cvta.to.shared.u64 t, %1; cvt.u32.u64 %0, t; }"
        : "=r"(a) : "l"(p));
    return a;
}
__device__ __forceinline__ void cp16(unsigned d, const void* g) {
    asm volatile("cp.async.cg.shared.global [%0], [%1], 16;" :: "r"(d), "l"(g));
}
__device__ __forceinline__ void ldm_x4(unsigned* r, unsigned addr) {
    asm volatile("ldmatrix.sync.aligned.m8n8.x4.shared.b16 {%0,%1,%2,%3}, [%4];"
                 : "=r"(r[0]), "=r"(r[1]), "=r"(r[2]), "=r"(r[3]) : "r"(addr));
}
__device__ __forceinline__ void mma16816(float* d, const unsigned* a,
                                         unsigned b0, unsigned b1) {
    asm volatile(
        "mma.sync.aligned.m16n8k16.row.col.f32.f16.f16.f32 "
        "{%0,%1,%2,%3}, {%4,%5,%6,%7}, {%8,%9}, {%0,%1,%2,%3};"
        : "+f"(d[0]), "+f"(d[1]), "+f"(d[2]), "+f"(d[3])
        : "r"(a[0]), "r"(a[1]), "r"(a[2]), "r"(a[3]), "r"(b0), "r"(b1));
}
__device__ __forceinline__ void fma2(unsigned long long& d, unsigned long long a,
                                     unsigned long long b) {
    asm("fma.rn.f32x2 %0, %1, %2, %0;" : "+l"(d) : "l"(a), "l"(b));
}
__device__ __forceinline__ unsigned long long bcast2(float x) {
    unsigned long long r;
    asm("mov.b64 %0, {%1, %1};" : "=l"(r) : "f"(x));
    return r;
}
__device__ __forceinline__ void unpack2(float& lo, float& hi,
                                        unsigned long long v) {
    asm("mov.b64 {%0, %1}, %2;" : "=f"(lo), "=f"(hi) : "l"(v));
}

// ---------------- generic HMMA GEMM core -------------------------------------
template <int NP, int KCH, int STRIDE, typename E>
__device__ __forceinline__ void gemm_run(const __half* const* Al,
                                         const __half* const* Bl,
                                         const signed char* pi,
                                         const signed char* pj, E epi) {
    extern __shared__ __align__(128) char smem[];
    int tid = threadIdx.x, lane = tid & 31, warp = tid >> 5;
    int n0 = blockIdx.x * 128, m0 = blockIdx.y * 128;
    int wm = (warp & 1) * 64, wn = (warp >> 1) * 32;
    unsigned sbase = smem_u32(smem);
    float acc[4][4][4] = {};

    auto load = [&](int t, int s) {
        const __half* A = Al[pi[t / KCH]];
        const __half* B = Bl[pj[t / KCH]];
        int k0 = (t % KCH) * 64;
        unsigned sa = sbase + (unsigned)s * 32768u, sb = sa + 16384u;
#pragma unroll
        for (int i = 0; i < 4; i++) {
            int cid = tid + (i << 8);
            int r = cid >> 3, c = cid & 7;
            unsigned off = (unsigned)(r * 128 + ((c ^ (r & 7)) << 4));
            cp16(sa + off, (const char*)(A + (size_t)(m0 + r) * STRIDE + k0) + c * 16);
            cp16(sb + off, (const char*)(B + (size_t)(n0 + r) * STRIDE + k0) + c * 16);
        }
        asm volatile("cp.async.commit_group;" ::: "memory");
    };

    constexpr int T = NP * KCH;
    load(0, 0);
    load(1, 1);
#pragma unroll 1
    for (int t = 0; t < T; t++) {
        if (t + 1 < T) {
            asm volatile("cp.async.wait_group 1;" ::: "memory");
        } else {
            asm volatile("cp.async.wait_group 0;" ::: "memory");
        }
        __syncthreads();
        if (t + 2 < T) load(t + 2, (t + 2) % 3);
        unsigned sa = sbase + (unsigned)(t % 3) * 32768u, sb = sa + 16384u;
#pragma unroll
        for (int ks = 0; ks < 4; ks++) {
            int clo = ks * 2;
            unsigned a[4][4], b[2][4];
#pragma unroll
            for (int g = 0; g < 4; g++) {
                int row = wm + g * 16 + (lane & 15);
                int c = clo + (lane >> 4);
                ldm_x4(a[g], sa + row * 128 + ((c ^ (row & 7)) << 4));
            }
#pragma unroll
            for (int h = 0; h < 2; h++) {
                int row = wn + h * 16 + ((lane >> 4) << 3) + (lane & 7);
                int c = clo + ((lane >> 3) & 1);
                ldm_x4(b[h], sb + row * 128 + ((c ^ (row & 7)) << 4));
            }
#pragma unroll
            for (int i = 0; i < 4; i++)
#pragma unroll
                for (int j = 0; j < 4; j++) {
                    const unsigned* bf = &b[j >> 1][(j & 1) * 2];
                    mma16816(acc[i][j], a[i], bf[0], bf[1]);
                }
        }
        __syncthreads();
    }
#pragma unroll
    for (int i = 0; i < 4; i++) {
        int row = m0 + wm + i * 16 + (lane >> 2);
#pragma unroll
        for (int j = 0; j < 4; j++)
            epi(row, n0 + wn + j * 8 + (lane & 3) * 2, acc[i][j]);
    }
}

__device__ __forceinline__ __half2 mk_h(float a, float b) {
    return __halves2half2(__float2half(a), __float2half(b));
}
__device__ __forceinline__ __half2 mk_l(float a, __half ha, float b, __half hb) {
    return __halves2half2(__float2half(a - __half2float(ha)),
                          __float2half(b - __half2float(hb)));
}

static const __device__ signed char PI3[3] = {0, 0, 1};
static const __device__ signed char PJ3[3] = {0, 1, 0};

// GEMM1: ef = x @ w_down^T; also emit fp16 split of (ef + pos)
__global__ void __launch_bounds__(256) k_gemm1(const float* __restrict__ pos) {
    const __half* A[2] = {g_xh, g_xl};
    const __half* B[2] = {g_w1h, g_w1l};
    gemm_run<3, 16, 1024>(A, B, PI3, PJ3, [&](int row, int col, const float* a) {
#pragma unroll
        for (int hh = 0; hh < 2; hh++) {
            int r = row + hh * 8;
            float v0 = a[hh * 2] * INV512, v1 = a[hh * 2 + 1] * INV512;
            size_t o = (size_t)r * 1024 + col;
            *(float2*)(g_ef + o) = make_float2(v0, v1);
            float2 pv = *(const float2*)(pos + col);
            float s0 = v0 + pv.x, s1 = v1 + pv.y;
            __half2 h = mk_h(s0, s1);
            *(__half2*)(g_sh + o) = h;
            *(__half2*)(g_sl + o) = mk_l(s0, __low2half(h), s1, __high2half(h));
        }
    });
}

// qkv GEMM: (8N,128) seq @ attn_in_w^T -> (8N,384) + bias
__global__ void __launch_bounds__(256) k_qkvg(const float* __restrict__ aib) {
    const __half* A[2] = {g_sh, g_sl};
    const __half* B[2] = {g_aih, g_ail};
    gemm_run<3, 2, 128>(A, B, PI3, PJ3, [&](int row, int col, const float* a) {
        float2 bv = *(const float2*)(aib + col);
#pragma unroll
        for (int hh = 0; hh < 2; hh++) {
            int r = row + hh * 8;
            *(float2*)(g_qkv + (size_t)r * 384 + col) =
                make_float2(a[hh * 2] * INV512 + bv.x,
                            a[hh * 2 + 1] * INV512 + bv.y);
        }
    });
}

// GEMM2: out = Ahat @ w_up
__global__ void __launch_bounds__(256) k_gemm2(float* __restrict__ C) {
    const __half* A[2] = {g_ah, g_al};
    const __half* B[2] = {g_w2h, g_w2l};
    gemm_run<3, 16, 1024>(A, B, PI3, PJ3, [&](int row, int col, const float* a) {
#pragma unroll
        for (int hh = 0; hh < 2; hh++)
            *(float2*)(C + (size_t)(row + hh * 8) * 1024 + col) =
                make_float2(a[hh * 2] * INV512, a[hh * 2 + 1] * INV512);
    });
}

// ---------------- split kernels ----------------------------------------------
__device__ __forceinline__ void split2_core(float4 v, float scale,
                                            __half* dh, __half* dl, size_t i) {
    float vs[4] = {v.x * scale, v.y * scale, v.z * scale, v.w * scale};
    __half2 h0 = mk_h(vs[0], vs[1]), h1 = mk_h(vs[2], vs[3]);
    ((__half2*)dh)[2 * i] = h0;
    ((__half2*)dh)[2 * i + 1] = h1;
    ((__half2*)dl)[2 * i] = mk_l(vs[0], __low2half(h0), vs[1], __high2half(h0));
    ((__half2*)dl)[2 * i + 1] = mk_l(vs[2], __low2half(h1), vs[3], __high2half(h1));
}
__global__ void k_split2_x(const float* __restrict__ x) {
    size_t i = (size_t)blockIdx.x * blockDim.x + threadIdx.x;
    split2_core(((const float4*)x)[i], 1.0f, g_xh, g_xl, i);
}
__global__ void k_split2_w1(const float* __restrict__ w) {
    size_t i = (size_t)blockIdx.x * blockDim.x + threadIdx.x;
    split2_core(((const float4*)w)[i], 512.0f, g_w1h, g_w1l, i);
}
__global__ void k_tsplit2_wup(const float* __restrict__ wup) {
    __shared__ float tile[32][33];
    int k0 = blockIdx.y * 32, m0 = blockIdx.x * 32;
    int tx = threadIdx.x, ty = threadIdx.y;
#pragma unroll
    for (int i = 0; i < 32; i += 8)
        tile[ty + i][tx] = wup[(size_t)(k0 + ty + i) * 1024 + m0 + tx];
    __syncthreads();
#pragma unroll
    for (int i = 0; i < 32; i += 8) {
        float v = tile[tx][ty + i] * 512.0f;
        __half h = __float2half(v);
        size_t o = (size_t)(m0 + ty + i) * 1024 + k0 + tx;
        g_w2h[o] = h;
        g_w2l[o] = __float2half(v - __half2float(h));
    }
}

// ---------------- prep -------------------------------------------------------
__global__ void k_prep(const float* __restrict__ aow,
                       const float* __restrict__ rkw,
                       const float* __restrict__ aiw) {
    int idx = blockIdx.x * blockDim.x + threadIdx.x;
    if (idx < BBATCH * DIM) g_xmean[idx] = 0.0f;
    if (idx < DLS * DLS) {
        g_wt_out[(idx % DLS) * DLS + idx / DLS] = aow[idx];
        g_wt_rk[(idx % DLS) * DLS + idx / DLS] = rkw[idx];
    }
    if (idx < 384 * DLS) {
        float v = aiw[idx] * 512.0f;
        __half h = __float2half(v);
        g_aih[idx] = h;
        g_ail[idx] = __float2half(v - __half2float(h));
    }
}

__global__ void k_colmean(const float* __restrict__ x) {
    int b = blockIdx.y, tc = blockIdx.x, tid = threadIdx.x;
    const float* xb = x + (size_t)b * TT * DIM + (size_t)tc * 128 * DIM;
    float acc[4] = {0.f, 0.f, 0.f, 0.f};
    for (int t = 0; t < 128; t++) {
        const float* row = xb + (size_t)t * DIM + tid;
#pragma unroll
        for (int i = 0; i < 4; i++) acc[i] += row[i * 256];
    }
#pragma unroll
    for (int i = 0; i < 4; i++)
        atomicAdd(&g_xmean[b * DIM + tid + i * 256], acc[i]);
}

// ---------------- gctx + k0/v0 + routing constants (u-trick) -----------------
__global__ void __launch_bounds__(1024) k_gctx_rq2(
    const float* __restrict__ gpw, const float* __restrict__ gpb,
    const float* __restrict__ rq1w, const float* __restrict__ rq1b,
    const float* __restrict__ rqlnw, const float* __restrict__ rqlnb,
    const float* __restrict__ rq2w, const float* __restrict__ rq2b,
    const float* __restrict__ aiw, const float* __restrict__ aib,
    const float* __restrict__ nw, const float* __restrict__ nb,
    const float* __restrict__ rkb) {
    __shared__ float sx[DIM];
    __shared__ float sg[DLS], st[DLS], sh[DLS];
    __shared__ float srq[DLS], su[DLS], svv[DLS];
    __shared__ float sred[8];
    int b = blockIdx.x, t = threadIdx.x;
    sx[t] = g_xmean[b * DIM + t] * (1.0f / TT);
    __syncthreads();
    int c = t >> 3, seg = t & 7;
    {
        float acc = 0.f;
        const float4* w4 = (const float4*)(gpw + (size_t)c * DIM + seg * 128);
        const float4* x4 = (const float4*)(sx + seg * 128);
#pragma unroll 8
        for (int i = 0; i < 32; i++) {
            float4 w = w4[i], xx = x4[i];
            acc += w.x * xx.x + w.y * xx.y + w.z * xx.z + w.w * xx.w;
        }
        acc += __shfl_down_sync(0xffffffffu, acc, 4, 8);
        acc += __shfl_down_sync(0xffffffffu, acc, 2, 8);
        acc += __shfl_down_sync(0xffffffffu, acc, 1, 8);
        if (seg == 0) {
            float gc = acc + gpb[c];
            sg[c] = gc;
            g_gctx[b * DLS + c] = gc;
        }
    }
    __syncthreads();
    {
        float acc = 0.f;
        const float4* w4 = (const float4*)(rq1w + (size_t)c * DLS + seg * 16);
        const float4* x4 = (const float4*)(sg + seg * 16);
#pragma unroll
        for (int i = 0; i < 4; i++) {
            float4 w = w4[i], xx = x4[i];
            acc += w.x * xx.x + w.y * xx.y + w.z * xx.z + w.w * xx.w;
        }
        acc += __shfl_down_sync(0xffffffffu, acc, 4, 8);
        acc += __shfl_down_sync(0xffffffffu, acc, 2, 8);
        acc += __shfl_down_sync(0xffffffffu, acc, 1, 8);
        if (seg == 0) st[c] = acc + rq1b[c];
    }
    {
        float acc = 0.f;
        const float4* w4 = (const float4*)(aiw + (size_t)(DLS + c) * DLS + seg * 16);
        const float4* x4 = (const float4*)(sg + seg * 16);
#pragma unroll
        for (int i = 0; i < 4; i++) {
            float4 w = w4[i], xx = x4[i];
            acc += w.x * xx.x + w.y * xx.y + w.z * xx.z + w.w * xx.w;
        }
        acc += __shfl_down_sync(0xffffffffu, acc, 4, 8);
        acc += __shfl_down_sync(0xffffffffu, acc, 2, 8);
        acc += __shfl_down_sync(0xffffffffu, acc, 1, 8);
        if (seg == 0) g_k0[b * DLS + c] = acc + aib[DLS + c];
    }
    {
        float acc = 0.f;
        const float4* w4 = (const float4*)(aiw + (size_t)(2 * DLS + c) * DLS + seg * 16);
        const float4* x4 = (const float4*)(sg + seg * 16);
#pragma unroll
        for (int i = 0; i < 4; i++) {
            float4 w = w4[i], xx = x4[i];
            acc += w.x * xx.x + w.y * xx.y + w.z * xx.z + w.w * xx.w;
        }
        acc += __shfl_down_sync(0xffffffffu, acc, 4, 8);
        acc += __shfl_down_sync(0xffffffffu, acc, 2, 8);
        acc += __shfl_down_sync(0xffffffffu, acc, 1, 8);
        if (seg == 0) g_v0[b * DLS + c] = acc + aib[2 * DLS + c];
    }
    __syncthreads();
    if (t < DLS) {
        float v = st[t];
        float s = v, q = v * v;
#pragma unroll
        for (int o = 16; o > 0; o >>= 1) {
            s += __shfl_down_sync(0xffffffffu, s, o);
            q += __shfl_down_sync(0xffffffffu, q, o);
        }
        if ((t & 31) == 0) { sred[t >> 5] = s; sred[4 + (t >> 5)] = q; }
    }
    __syncthreads();
    if (t < DLS) {
        float s = sred[0] + sred[1] + sred[2] + sred[3];
        float q = sred[4] + sred[5] + sred[6] + sred[7];
        float mu = s * (1.0f / 128.0f);
        float var = q * (1.0f / 128.0f) - mu * mu;
        float h = (st[t] - mu) * rsqrtf(var + 1e-5f) * rqlnw[t] + rqlnb[t];
        sh[t] = gelu_f(h);
    }
    __syncthreads();
    {   // rq[c]
        float acc = 0.f;
        const float4* w4 = (const float4*)(rq2w + (size_t)c * DLS + seg * 16);
        const float4* x4 = (const float4*)(sh + seg * 16);
#pragma unroll
        for (int i = 0; i < 4; i++) {
            float4 w = w4[i], xx = x4[i];
            acc += w.x * xx.x + w.y * xx.y + w.z * xx.z + w.w * xx.w;
        }
        acc += __shfl_down_sync(0xffffffffu, acc, 4, 8);
        acc += __shfl_down_sync(0xffffffffu, acc, 2, 8);
        acc += __shfl_down_sync(0xffffffffu, acc, 1, 8);
        if (seg == 0) srq[c] = acc + rq2b[c];
    }
    __syncthreads();
    {   // u[d] = sum_c rk_w[c][d] * rq[c] = g_wt_rk[d][:] . rq
        float acc = 0.f;
        const float4* w4 = (const float4*)(g_wt_rk + (size_t)c * DLS + seg * 16);
        const float4* x4 = (const float4*)(srq + seg * 16);
#pragma unroll
        for (int i = 0; i < 4; i++) {
            float4 w = w4[i], xx = x4[i];
            acc += w.x * xx.x + w.y * xx.y + w.z * xx.z + w.w * xx.w;
        }
        acc += __shfl_down_sync(0xffffffffu, acc, 4, 8);
        acc += __shfl_down_sync(0xffffffffu, acc, 2, 8);
        acc += __shfl_down_sync(0xffffffffu, acc, 1, 8);
        if (seg == 0) {
            su[c] = acc;
            float vvv = nw[c] * acc;
            svv[c] = vvv;
            g_vv[b * DLS + c] = vvv;
        }
    }
    __syncthreads();
    if (t < 32) {
        float a = 0.f, bb = 0.f, ss = 0.f;
#pragma unroll
        for (int k = 0; k < 4; k++) {
            int d = t + k * 32;
            a += svv[d];
            bb += nb[d] * su[d];
            ss += srq[d] * rkb[d];
        }
#pragma unroll
        for (int o = 16; o > 0; o >>= 1) {
            a += __shfl_down_sync(0xffffffffu, a, o);
            bb += __shfl_down_sync(0xffffffffu, bb, o);
            ss += __shfl_down_sync(0xffffffffu, ss, o);
        }
        if (t == 0) {
            g_sc[b * 2] = a;            // alpha = sum(v)
            g_sc[b * 2 + 1] = bb + ss;  // gamma = nb.u + rq.rkb
        }
    }
}

// ---------------- per-token: attention + router (rk eliminated) --------------
__global__ void __launch_bounds__(128) k_attn(
    const float* __restrict__ pos, const float* __restrict__ aob) {
    __shared__ float s_q[8][129];
    __shared__ float s_k[S9][DLS];
    __shared__ float s_v[S9][DLS];
    __shared__ __align__(16) float s_oT[DLS][10];
    __shared__ float s_s2[8][DLS];
    __shared__ float s_vv[DLS];
    __shared__ float s_logit[8], s_coef[NE];

    int n = blockIdx.x, b = n >> 11, c = threadIdx.x;
    int w = c >> 5, lane = c & 31;
    float alpha = g_sc[b * 2], gamma = g_sc[b * 2 + 1];

    float efv[8];
#pragma unroll
    for (int e = 0; e < 8; e++) efv[e] = g_ef[(size_t)n * DIM + e * DLS + c];
    const float* qb = g_qkv + (size_t)n * 8 * 384;
#pragma unroll
    for (int e = 0; e < 8; e++) {
        s_q[e][c] = qb[e * 384 + c];
        s_k[1 + e][c] = qb[e * 384 + 128 + c];
        s_v[1 + e][c] = qb[e * 384 + 256 + c];
    }
    s_k[0][c] = g_k0[b * DLS + c];
    s_v[0][c] = g_v0[b * DLS + c];
    s_vv[c] = g_vv[b * DLS + c];
    __syncthreads();

    if (lane < 8) {
        int h = w;
        const float scale = 0.17677669529663688f;
        float qreg[HDV];
#pragma unroll
        for (int dd = 0; dd < HDV; dd++) qreg[dd] = s_q[lane][h * HDV + dd];
        float sc[S9];
#pragma unroll
        for (int j = 0; j < S9; j++) {
            float s = 0.f;
#pragma unroll
            for (int dd = 0; dd < HDV; dd++) s += qreg[dd] * s_k[j][h * HDV + dd];
            sc[j] = s * scale;
        }
        float m = sc[0];
#pragma unroll
        for (int j = 1; j < S9; j++) m = fmaxf(m, sc[j]);
        float ssum = 0.f;
#pragma unroll
        for (int j = 0; j < S9; j++) { sc[j] = expf(sc[j] - m); ssum += sc[j]; }
        float inv = 1.0f / ssum;
#pragma unroll
        for (int dd = 0; dd < HDV; dd++) {
            float o = 0.f;
#pragma unroll
            for (int j = 0; j < S9; j++) o += sc[j] * s_v[j][h * HDV + dd];
            s_oT[h * HDV + dd][lane] = o * inv;
        }
    }
    __syncthreads();

    // out proj + bias + residual -> s2 rows
    {
        float seqv[8];
#pragma unroll
        for (int e = 0; e < 8; e++) seqv[e] = efv[e] + pos[e * DLS + c];
        unsigned long long po[4] = {};
#pragma unroll 2
        for (int d = 0; d < DLS; d++) {
            unsigned long long wp = bcast2(g_wt_out[d * DLS + c]);
            const unsigned long long* sp = (const unsigned long long*)&s_oT[d][0];
#pragma unroll
            for (int p = 0; p < 4; p++) fma2(po[p], sp[p], wp);
        }
        float bo = aob[c];
#pragma unroll
        for (int p = 0; p < 4; p++) {
            float lo, hi;
            unpack2(lo, hi, po[p]);
            s_s2[2 * p][c] = lo + bo + seqv[2 * p];
            s_s2[2 * p + 1][c] = hi + bo + seqv[2 * p + 1];
        }
    }
    __syncthreads();

    // per-row (sum, sumsq, dot-with-v) -> logit directly
    for (int r = w; r < 8; r += 4) {
        float s = 0.f, q = 0.f, t1 = 0.f;
#pragma unroll
        for (int k = 0; k < 4; k++) {
            float v = s_s2[r][lane + 32 * k];
            float vv = s_vv[lane + 32 * k];
            s += v;
            q += v * v;
            t1 += v * vv;
        }
#pragma unroll
        for (int o = 16; o > 0; o >>= 1) {
            s += __shfl_down_sync(0xffffffffu, s, o);
            q += __shfl_down_sync(0xffffffffu, q, o);
            t1 += __shfl_down_sync(0xffffffffu, t1, o);
        }
        if (lane == 0) {
            float mu = s * (1.0f / 128.0f);
            float var = q * (1.0f / 128.0f) - mu * mu;
            float rs = rsqrtf(var + 1e-5f);
            s_logit[r] = (rs * (t1 - mu * alpha) + gamma) * 0.08838834764831845f;
        }
    }
    __syncthreads();

    if (c == 0) {
        float p[NE];
        float m = -1e30f;
#pragma unroll
        for (int e = 0; e < NE; e++) m = fmaxf(m, s_logit[e]);
        float sum = 0.f;
#pragma unroll
        for (int e = 0; e < NE; e++) { p[e] = expf(s_logit[e] - m); sum += p[e]; }
        float inv = 1.0f / sum;
#pragma unroll
        for (int e = 0; e < NE; e++) {
            p[e] *= inv;
            g_probs[n * NE + e] = p[e];
            s_coef[e] = 0.f;
        }
        int sel[3];
        float tw[3];
        bool used[NE] = {};
#pragma unroll
        for (int t = 0; t < 3; t++) {
            int bi = 0;
            float bv = -1.f;
#pragma unroll
            for (int e = 0; e < NE; e++)
                if (!used[e] && p[e] > bv) { bv = p[e]; bi = e; }
            used[bi] = true;
            sel[t] = bi;
            tw[t] = bv;
        }
        float tinv = 1.0f / (tw[0] + tw[1] + tw[2]);
#pragma unroll
        for (int t = 0; t < 3; t++) s_coef[sel[t]] = tw[t] * tinv;
#pragma unroll
        for (int e = 0; e < NE; e++) g_coef[n * NE + e] = s_coef[e];
    }
    __syncthreads();

#pragma unroll
    for (int e = 0; e < NE; e++) {
        size_t idx = (size_t)n * DIM + e * DLS + c;
        float a = s_coef[e] * gelu_f(efv[e]);
        __half h = __float2half(a);
        g_ah[idx] = h;
        g_al[idx] = __float2half(a - __half2float(h));
    }
}

// ---------------- aux loss ---------------------------------------------------
__global__ void k_aux(float* __restrict__ out) {
    __shared__ float sp[256 * 8];
    __shared__ float sc2[256 * 8];
    int tid = threadIdx.x;
    float ps[NE], cs[NE];
#pragma unroll
    for (int e = 0; e < NE; e++) { ps[e] = 0.f; cs[e] = 0.f; }
    for (int nn = tid; nn < NTOK; nn += 256) {
#pragma unroll
        for (int e = 0; e < NE; e++) {
            ps[e] += g_probs[nn * NE + e];
            cs[e] += (g_coef[nn * NE + e] > 0.f) ? 1.0f : 0.0f;
        }
    }
#pragma unroll
    for (int e = 0; e < NE; e++) {
        sp[e * 256 + tid] = ps[e];
        sc2[e * 256 + tid] = cs[e];
    }
    __syncthreads();
    if (tid < NE) {
        float a = 0.f, bsum = 0.f;
        for (int i = 0; i < 256; i++) {
            a += sp[tid * 256 + i];
            bsum += sc2[tid * 256 + i];
        }
        sp[tid] = a;
        sc2[tid] = bsum;
    }
    __syncthreads();
    if (tid == 0) {
        float aux = 0.f;
        for (int e = 0; e < NE; e++)
            aux += (sp[e] * (1.0f / NTOK)) * (sc2[e] * (1.0f / NTOK));
        out[(size_t)NTOK * DIM] = 8.0f * aux;
    }
}

// ---------------- launch -----------------------------------------------------
extern "C" void kernel_launch(void* const* d_in, const int* in_sizes, int n_in,
                              void* d_out, int out_size) {
    const float* x    = (const float*)d_in[0];
    const float* wdn  = (const float*)d_in[1];
    const float* pos  = (const float*)d_in[2];
    const float* gpw  = (const float*)d_in[3];
    const float* gpb  = (const float*)d_in[4];
    const float* aiw  = (const float*)d_in[5];
    const float* aib  = (const float*)d_in[6];
    const float* aow  = (const float*)d_in[7];
    const float* aob  = (const float*)d_in[8];
    const float* nw   = (const float*)d_in[9];
    const float* nb   = (const float*)d_in[10];
    const float* rq1w = (const float*)d_in[11];
    const float* rq1b = (const float*)d_in[12];
    const float* rqlnw= (const float*)d_in[13];
    const float* rqlnb= (const float*)d_in[14];
    const float* rq2w = (const float*)d_in[15];
    const float* rq2b = (const float*)d_in[16];
    const float* rkw  = (const float*)d_in[17];
    const float* rkb  = (const float*)d_in[18];
    const float* wup  = (const float*)d_in[19];
    float* out = (float*)d_out;

    const int SMEM = 3 * 32768;
    cudaFuncSetAttribute(k_gemm1, cudaFuncAttributeMaxDynamicSharedMemorySize, SMEM);
    cudaFuncSetAttribute(k_qkvg, cudaFuncAttributeMaxDynamicSharedMemorySize, SMEM);
    cudaFuncSetAttribute(k_gemm2, cudaFuncAttributeMaxDynamicSharedMemorySize, SMEM);

    k_prep<<<192, 256>>>(aow, rkw, aiw);
    k_split2_x<<<8192, 256>>>(x);
    k_split2_w1<<<1024, 256>>>(wdn);
    k_tsplit2_wup<<<dim3(32, 32), dim3(32, 8)>>>(wup);
    k_colmean<<<dim3(16, BBATCH), 256>>>(x);
    k_gctx_rq2<<<BBATCH, 1024>>>(gpw, gpb, rq1w, rq1b, rqlnw, rqlnb, rq2w, rq2b,
                                 aiw, aib, nw, nb, rkb);
    k_gemm1<<<dim3(8, 64), 256, SMEM>>>(pos);
    k_qkvg<<<dim3(3, 512), 256, SMEM>>>(aib);
    k_attn<<<NTOK, 128>>>(pos, aob);
    k_gemm2<<<dim3(8, 64), 256, SMEM>>>(out);
    k_aux<<<1, 256>>>(out);
}

// round 15
// speedup vs baseline: 1.6125x; 1.0083x over previous
#include <cuda_runtime.h>
#include <cuda_fp16.h>
#include <math.h>

#define NTOK 8192
#define DIM  1024
#define DLS  128
#define NE   8
#define HDV  32
#define TT   2048
#define BBATCH 4
#define S9   9
#define INV512 (1.0f / 512.0f)

// ---------------- scratch ----------------------------------------------------
__device__ float g_ef[NTOK * DIM];
__device__ float g_qkv[NTOK * NE * 384];
__device__ float g_xmean[BBATCH * DIM];
__device__ float g_gctx[BBATCH * DLS];
__device__ float g_k0[BBATCH * DLS];
__device__ float g_v0[BBATCH * DLS];
__device__ float g_vv[BBATCH * DLS];   // v = nw ⊙ (rq @ rk_w)
__device__ float g_sc[BBATCH * 2];     // alpha, gamma
__device__ float g_probs[NTOK * NE];
__device__ float g_coef[NTOK * NE];
__device__ float g_wt_out[DLS * DLS];
__device__ float g_wt_rk[DLS * DLS];   // [d][c] = rk_w[c][d]

__device__ __align__(16) __half g_xh[NTOK * DIM];
__device__ __align__(16) __half g_xl[NTOK * DIM];
__device__ __align__(16) __half g_w1h[DIM * DIM];   // w_down * 512
__device__ __align__(16) __half g_w1l[DIM * DIM];
__device__ __align__(16) __half g_sh[NTOK * DIM];   // seq = ef + pos (8N x 128)
__device__ __align__(16) __half g_sl[NTOK * DIM];
__device__ __align__(16) __half g_aih[384 * DLS];   // attn_in_w * 512
__device__ __align__(16) __half g_ail[384 * DLS];
__device__ __align__(16) __half g_ah[NTOK * DIM];   // coef*gelu(ef)
__device__ __align__(16) __half g_al[NTOK * DIM];
__device__ __align__(16) __half g_w2h[DIM * DIM];   // w_up^T * 512
__device__ __align__(16) __half g_w2l[DIM * DIM];

__device__ __forceinline__ float gelu_f(float x) {
    return 0.5f * x * (1.0f + erff(x * 0.70710678118654752440f));
}

// ---------------- PTX helpers ------------------------------------------------
__device__ __forceinline__ unsigned smem_u32(const void* p) {
    unsigned a;
    asm("{ .reg .u64 t; cvta.to.shared.u64 t, %1; cvt.u32.u64 %0, t; }"
        : "=r"(a) : "l"(p));
    return a;
}
__device__ __forceinline__ void cp16(unsigned d, const void* g) {
    asm volatile("cp.async.cg.shared.global [%0], [%1], 16;" :: "r"(d), "l"(g));
}
__device__ __forceinline__ void ldm_x4(unsigned* r, unsigned addr) {
    asm volatile("ldmatrix.sync.aligned.m8n8.x4.shared.b16 {%0,%1,%2,%3}, [%4];"
                 : "=r"(r[0]), "=r"(r[1]), "=r"(r[2]), "=r"(r[3]) : "r"(addr));
}
__device__ __forceinline__ void mma16816(float* d, const unsigned* a,
                                         unsigned b0, unsigned b1) {
    asm volatile(
        "mma.sync.aligned.m16n8k16.row.col.f32.f16.f16.f32 "
        "{%0,%1,%2,%3}, {%4,%5,%6,%7}, {%8,%9}, {%0,%1,%2,%3};"
        : "+f"(d[0]), "+f"(d[1]), "+f"(d[2]), "+f"(d[3])
        : "r"(a[0]), "r"(a[1]), "r"(a[2]), "r"(a[3]), "r"(b0), "r"(b1));
}
__device__ __forceinline__ void fma2(unsigned long long& d, unsigned long long a,
                                     unsigned long long b) {
    asm("fma.rn.f32x2 %0, %1, %2, %0;" : "+l"(d) : "l"(a), "l"(b));
}
__device__ __forceinline__ unsigned long long bcast2(float x) {
    unsigned long long r;
    asm("mov.b64 %0, {%1, %1};" : "=l"(r) : "f"(x));
    return r;
}
__device__ __forceinline__ void unpack2(float& lo, float& hi,
                                        unsigned long long v) {
    asm("mov.b64 {%0, %1}, %2;" : "=f"(lo), "=f"(hi) : "l"(v));
}

// ---------------- shared-operand split-GEMM core -----------------------------
// acc = A0.B0^T + A0.B1^T + A1.B0^T over K = KCH*64. Stage holds all 4 tiles
// (64KB); 3-stage ring; ONE sync per chunk (leading sync orders ring reuse).
template <int KCH, int STRIDE, typename E>
__device__ __forceinline__ void gemm_run(const __half* __restrict__ A0p,
                                         const __half* __restrict__ A1p,
                                         const __half* __restrict__ B0p,
                                         const __half* __restrict__ B1p,
                                         E epi) {
    extern __shared__ __align__(128) char smem[];
    int tid = threadIdx.x, lane = tid & 31, warp = tid >> 5;
    int n0 = blockIdx.x * 128, m0 = blockIdx.y * 128;
    int wm = (warp & 1) * 64, wn = (warp >> 1) * 32;
    unsigned sbase = smem_u32(smem);
    float acc[4][4][4] = {};

    auto load = [&](int ch, int s) {
        int k0 = ch * 64;
        unsigned st = sbase + (unsigned)s * 65536u;
#pragma unroll
        for (int i = 0; i < 4; i++) {
            int cid = tid + (i << 8);
            int r = cid >> 3, c = cid & 7;
            unsigned off = (unsigned)(r * 128 + ((c ^ (r & 7)) << 4));
            const char* ga = (const char*)(A0p + (size_t)(m0 + r) * STRIDE + k0) + c * 16;
            const char* gA1 = (const char*)(A1p + (size_t)(m0 + r) * STRIDE + k0) + c * 16;
            const char* gb = (const char*)(B0p + (size_t)(n0 + r) * STRIDE + k0) + c * 16;
            const char* gB1 = (const char*)(B1p + (size_t)(n0 + r) * STRIDE + k0) + c * 16;
            cp16(st + off, ga);
            cp16(st + 16384u + off, gA1);
            cp16(st + 32768u + off, gb);
            cp16(st + 49152u + off, gB1);
        }
        asm volatile("cp.async.commit_group;" ::: "memory");
    };

    load(0, 0);
    if (KCH > 1) load(1, 1);
#pragma unroll 1
    for (int t = 0; t < KCH; t++) {
        if (t + 1 < KCH) {
            asm volatile("cp.async.wait_group 1;" ::: "memory");
        } else {
            asm volatile("cp.async.wait_group 0;" ::: "memory");
        }
        __syncthreads();
        if (t + 2 < KCH) load(t + 2, (t + 2) % 3);
        unsigned st = sbase + (unsigned)(t % 3) * 65536u;
        unsigned sa0 = st, sa1 = st + 16384u, sb0 = st + 32768u,
                 sb1 = st + 49152u;
#pragma unroll
        for (int ks = 0; ks < 4; ks++) {
            int clo = ks * 2;
            unsigned a0[4][4], a1[4][4], b0[2][4], b1[2][4];
#pragma unroll
            for (int g = 0; g < 4; g++) {
                int row = wm + g * 16 + (lane & 15);
                int c = clo + (lane >> 4);
                unsigned off = (unsigned)(row * 128 + ((c ^ (row & 7)) << 4));
                ldm_x4(a0[g], sa0 + off);
            }
#pragma unroll
            for (int h = 0; h < 2; h++) {
                int row = wn + h * 16 + ((lane >> 4) << 3) + (lane & 7);
                int c = clo + ((lane >> 3) & 1);
                unsigned off = (unsigned)(row * 128 + ((c ^ (row & 7)) << 4));
                ldm_x4(b0[h], sb0 + off);
                ldm_x4(b1[h], sb1 + off);
            }
#pragma unroll
            for (int g = 0; g < 4; g++) {
                int row = wm + g * 16 + (lane & 15);
                int c = clo + (lane >> 4);
                unsigned off = (unsigned)(row * 128 + ((c ^ (row & 7)) << 4));
                ldm_x4(a1[g], sa1 + off);
            }
#pragma unroll
            for (int i = 0; i < 4; i++)
#pragma unroll
                for (int j = 0; j < 4; j++) {
                    const unsigned* f0 = &b0[j >> 1][(j & 1) * 2];
                    const unsigned* f1 = &b1[j >> 1][(j & 1) * 2];
                    mma16816(acc[i][j], a0[i], f0[0], f0[1]);
                    mma16816(acc[i][j], a0[i], f1[0], f1[1]);
                    mma16816(acc[i][j], a1[i], f0[0], f0[1]);
                }
        }
    }
#pragma unroll
    for (int i = 0; i < 4; i++) {
        int row = m0 + wm + i * 16 + (lane >> 2);
#pragma unroll
        for (int j = 0; j < 4; j++)
            epi(row, n0 + wn + j * 8 + (lane & 3) * 2, acc[i][j]);
    }
}

__device__ __forceinline__ __half2 mk_h(float a, float b) {
    return __halves2half2(__float2half(a), __float2half(b));
}
__device__ __forceinline__ __half2 mk_l(float a, __half ha, float b, __half hb) {
    return __halves2half2(__float2half(a - __half2float(ha)),
                          __float2half(b - __half2float(hb)));
}

// GEMM1: ef = x @ w_down^T; also emit fp16 split of (ef + pos)
__global__ void __launch_bounds__(256) k_gemm1(const float* __restrict__ pos) {
    gemm_run<16, 1024>(g_xh, g_xl, g_w1h, g_w1l,
                       [&](int row, int col, const float* a) {
#pragma unroll
        for (int hh = 0; hh < 2; hh++) {
            int r = row + hh * 8;
            float v0 = a[hh * 2] * INV512, v1 = a[hh * 2 + 1] * INV512;
            size_t o = (size_t)r * 1024 + col;
            *(float2*)(g_ef + o) = make_float2(v0, v1);
            float2 pv = *(const float2*)(pos + col);
            float s0 = v0 + pv.x, s1 = v1 + pv.y;
            __half2 h = mk_h(s0, s1);
            *(__half2*)(g_sh + o) = h;
            *(__half2*)(g_sl + o) = mk_l(s0, __low2half(h), s1, __high2half(h));
        }
    });
}

// qkv GEMM: (8N,128) seq @ attn_in_w^T -> (8N,384) + bias
__global__ void __launch_bounds__(256) k_qkvg(const float* __restrict__ aib) {
    gemm_run<2, 128>(g_sh, g_sl, g_aih, g_ail,
                     [&](int row, int col, const float* a) {
        float2 bv = *(const float2*)(aib + col);
#pragma unroll
        for (int hh = 0; hh < 2; hh++) {
            int r = row + hh * 8;
            *(float2*)(g_qkv + (size_t)r * 384 + col) =
                make_float2(a[hh * 2] * INV512 + bv.x,
                            a[hh * 2 + 1] * INV512 + bv.y);
        }
    });
}

// GEMM2: out = Ahat @ w_up
__global__ void __launch_bounds__(256) k_gemm2(float* __restrict__ C) {
    gemm_run<16, 1024>(g_ah, g_al, g_w2h, g_w2l,
                       [&](int row, int col, const float* a) {
#pragma unroll
        for (int hh = 0; hh < 2; hh++)
            *(float2*)(C + (size_t)(row + hh * 8) * 1024 + col) =
                make_float2(a[hh * 2] * INV512, a[hh * 2 + 1] * INV512);
    });
}

// ---------------- split kernels ----------------------------------------------
__device__ __forceinline__ void split2_core(float4 v, float scale,
                                            __half* dh, __half* dl, size_t i) {
    float vs[4] = {v.x * scale, v.y * scale, v.z * scale, v.w * scale};
    __half2 h0 = mk_h(vs[0], vs[1]), h1 = mk_h(vs[2], vs[3]);
    ((__half2*)dh)[2 * i] = h0;
    ((__half2*)dh)[2 * i + 1] = h1;
    ((__half2*)dl)[2 * i] = mk_l(vs[0], __low2half(h0), vs[1], __high2half(h0));
    ((__half2*)dl)[2 * i + 1] = mk_l(vs[2], __low2half(h1), vs[3], __high2half(h1));
}
__global__ void k_split2_x(const float* __restrict__ x) {
    size_t i = (size_t)blockIdx.x * blockDim.x + threadIdx.x;
    split2_core(((const float4*)x)[i], 1.0f, g_xh, g_xl, i);
}
__global__ void k_split2_w1(const float* __restrict__ w) {
    size_t i = (size_t)blockIdx.x * blockDim.x + threadIdx.x;
    split2_core(((const float4*)w)[i], 512.0f, g_w1h, g_w1l, i);
}
__global__ void k_tsplit2_wup(const float* __restrict__ wup) {
    __shared__ float tile[32][33];
    int k0 = blockIdx.y * 32, m0 = blockIdx.x * 32;
    int tx = threadIdx.x, ty = threadIdx.y;
#pragma unroll
    for (int i = 0; i < 32; i += 8)
        tile[ty + i][tx] = wup[(size_t)(k0 + ty + i) * 1024 + m0 + tx];
    __syncthreads();
#pragma unroll
    for (int i = 0; i < 32; i += 8) {
        float v = tile[tx][ty + i] * 512.0f;
        __half h = __float2half(v);
        size_t o = (size_t)(m0 + ty + i) * 1024 + k0 + tx;
        g_w2h[o] = h;
        g_w2l[o] = __float2half(v - __half2float(h));
    }
}

// ---------------- prep -------------------------------------------------------
__global__ void k_prep(const float* __restrict__ aow,
                       const float* __restrict__ rkw,
                       const float* __restrict__ aiw) {
    int idx = blockIdx.x * blockDim.x + threadIdx.x;
    if (idx < BBATCH * DIM) g_xmean[idx] = 0.0f;
    if (idx < DLS * DLS) {
        g_wt_out[(idx % DLS) * DLS + idx / DLS] = aow[idx];
        g_wt_rk[(idx % DLS) * DLS + idx / DLS] = rkw[idx];
    }
    if (idx < 384 * DLS) {
        float v = aiw[idx] * 512.0f;
        __half h = __float2half(v);
        g_aih[idx] = h;
        g_ail[idx] = __float2half(v - __half2float(h));
    }
}

__global__ void k_colmean(const float* __restrict__ x) {
    int b = blockIdx.y, tc = blockIdx.x, tid = threadIdx.x;
    const float* xb = x + (size_t)b * TT * DIM + (size_t)tc * 128 * DIM;
    float acc[4] = {0.f, 0.f, 0.f, 0.f};
    for (int t = 0; t < 128; t++) {
        const float* row = xb + (size_t)t * DIM + tid;
#pragma unroll
        for (int i = 0; i < 4; i++) acc[i] += row[i * 256];
    }
#pragma unroll
    for (int i = 0; i < 4; i++)
        atomicAdd(&g_xmean[b * DIM + tid + i * 256], acc[i]);
}

// ---------------- gctx + k0/v0 + routing constants (u-trick) -----------------
__global__ void __launch_bounds__(1024) k_gctx_rq2(
    const float* __restrict__ gpw, const float* __restrict__ gpb,
    const float* __restrict__ rq1w, const float* __restrict__ rq1b,
    const float* __restrict__ rqlnw, const float* __restrict__ rqlnb,
    const float* __restrict__ rq2w, const float* __restrict__ rq2b,
    const float* __restrict__ aiw, const float* __restrict__ aib,
    const float* __restrict__ nw, const float* __restrict__ nb,
    const float* __restrict__ rkb) {
    __shared__ float sx[DIM];
    __shared__ float sg[DLS], st[DLS], sh[DLS];
    __shared__ float srq[DLS], su[DLS], svv[DLS];
    __shared__ float sred[8];
    int b = blockIdx.x, t = threadIdx.x;
    sx[t] = g_xmean[b * DIM + t] * (1.0f / TT);
    __syncthreads();
    int c = t >> 3, seg = t & 7;
    {
        float acc = 0.f;
        const float4* w4 = (const float4*)(gpw + (size_t)c * DIM + seg * 128);
        const float4* x4 = (const float4*)(sx + seg * 128);
#pragma unroll 8
        for (int i = 0; i < 32; i++) {
            float4 w = w4[i], xx = x4[i];
            acc += w.x * xx.x + w.y * xx.y + w.z * xx.z + w.w * xx.w;
        }
        acc += __shfl_down_sync(0xffffffffu, acc, 4, 8);
        acc += __shfl_down_sync(0xffffffffu, acc, 2, 8);
        acc += __shfl_down_sync(0xffffffffu, acc, 1, 8);
        if (seg == 0) {
            float gc = acc + gpb[c];
            sg[c] = gc;
            g_gctx[b * DLS + c] = gc;
        }
    }
    __syncthreads();
    {
        float acc = 0.f;
        const float4* w4 = (const float4*)(rq1w + (size_t)c * DLS + seg * 16);
        const float4* x4 = (const float4*)(sg + seg * 16);
#pragma unroll
        for (int i = 0; i < 4; i++) {
            float4 w = w4[i], xx = x4[i];
            acc += w.x * xx.x + w.y * xx.y + w.z * xx.z + w.w * xx.w;
        }
        acc += __shfl_down_sync(0xffffffffu, acc, 4, 8);
        acc += __shfl_down_sync(0xffffffffu, acc, 2, 8);
        acc += __shfl_down_sync(0xffffffffu, acc, 1, 8);
        if (seg == 0) st[c] = acc + rq1b[c];
    }
    {
        float acc = 0.f;
        const float4* w4 = (const float4*)(aiw + (size_t)(DLS + c) * DLS + seg * 16);
        const float4* x4 = (const float4*)(sg + seg * 16);
#pragma unroll
        for (int i = 0; i < 4; i++) {
            float4 w = w4[i], xx = x4[i];
            acc += w.x * xx.x + w.y * xx.y + w.z * xx.z + w.w * xx.w;
        }
        acc += __shfl_down_sync(0xffffffffu, acc, 4, 8);
        acc += __shfl_down_sync(0xffffffffu, acc, 2, 8);
        acc += __shfl_down_sync(0xffffffffu, acc, 1, 8);
        if (seg == 0) g_k0[b * DLS + c] = acc + aib[DLS + c];
    }
    {
        float acc = 0.f;
        const float4* w4 = (const float4*)(aiw + (size_t)(2 * DLS + c) * DLS + seg * 16);
        const float4* x4 = (const float4*)(sg + seg * 16);
#pragma unroll
        for (int i = 0; i < 4; i++) {
            float4 w = w4[i], xx = x4[i];
            acc += w.x * xx.x + w.y * xx.y + w.z * xx.z + w.w * xx.w;
        }
        acc += __shfl_down_sync(0xffffffffu, acc, 4, 8);
        acc += __shfl_down_sync(0xffffffffu, acc, 2, 8);
        acc += __shfl_down_sync(0xffffffffu, acc, 1, 8);
        if (seg == 0) g_v0[b * DLS + c] = acc + aib[2 * DLS + c];
    }
    __syncthreads();
    if (t < DLS) {
        float v = st[t];
        float s = v, q = v * v;
#pragma unroll
        for (int o = 16; o > 0; o >>= 1) {
            s += __shfl_down_sync(0xffffffffu, s, o);
            q += __shfl_down_sync(0xffffffffu, q, o);
        }
        if ((t & 31) == 0) { sred[t >> 5] = s; sred[4 + (t >> 5)] = q; }
    }
    __syncthreads();
    if (t < DLS) {
        float s = sred[0] + sred[1] + sred[2] + sred[3];
        float q = sred[4] + sred[5] + sred[6] + sred[7];
        float mu = s * (1.0f / 128.0f);
        float var = q * (1.0f / 128.0f) - mu * mu;
        float h = (st[t] - mu) * rsqrtf(var + 1e-5f) * rqlnw[t] + rqlnb[t];
        sh[t] = gelu_f(h);
    }
    __syncthreads();
    {
        float acc = 0.f;
        const float4* w4 = (const float4*)(rq2w + (size_t)c * DLS + seg * 16);
        const float4* x4 = (const float4*)(sh + seg * 16);
#pragma unroll
        for (int i = 0; i < 4; i++) {
            float4 w = w4[i], xx = x4[i];
            acc += w.x * xx.x + w.y * xx.y + w.z * xx.z + w.w * xx.w;
        }
        acc += __shfl_down_sync(0xffffffffu, acc, 4, 8);
        acc += __shfl_down_sync(0xffffffffu, acc, 2, 8);
        acc += __shfl_down_sync(0xffffffffu, acc, 1, 8);
        if (seg == 0) srq[c] = acc + rq2b[c];
    }
    __syncthreads();
    {
        float acc = 0.f;
        const float4* w4 = (const float4*)(g_wt_rk + (size_t)c * DLS + seg * 16);
        const float4* x4 = (const float4*)(srq + seg * 16);
#pragma unroll
        for (int i = 0; i < 4; i++) {
            float4 w = w4[i], xx = x4[i];
            acc += w.x * xx.x + w.y * xx.y + w.z * xx.z + w.w * xx.w;
        }
        acc += __shfl_down_sync(0xffffffffu, acc, 4, 8);
        acc += __shfl_down_sync(0xffffffffu, acc, 2, 8);
        acc += __shfl_down_sync(0xffffffffu, acc, 1, 8);
        if (seg == 0) {
            su[c] = acc;
            float vvv = nw[c] * acc;
            svv[c] = vvv;
            g_vv[b * DLS + c] = vvv;
        }
    }
    __syncthreads();
    if (t < 32) {
        float a = 0.f, bb = 0.f, ss = 0.f;
#pragma unroll
        for (int k = 0; k < 4; k++) {
            int d = t + k * 32;
            a += svv[d];
            bb += nb[d] * su[d];
            ss += srq[d] * rkb[d];
        }
#pragma unroll
        for (int o = 16; o > 0; o >>= 1) {
            a += __shfl_down_sync(0xffffffffu, a, o);
            bb += __shfl_down_sync(0xffffffffu, bb, o);
            ss += __shfl_down_sync(0xffffffffu, ss, o);
        }
        if (t == 0) {
            g_sc[b * 2] = a;
            g_sc[b * 2 + 1] = bb + ss;
        }
    }
}

// ---------------- per-token: attention + router ------------------------------
__global__ void __launch_bounds__(128) k_attn(
    const float* __restrict__ pos, const float* __restrict__ aob) {
    __shared__ float s_q[8][129];
    __shared__ float s_k[S9][DLS];
    __shared__ float s_v[S9][DLS];
    __shared__ __align__(16) float s_oT[DLS][10];
    __shared__ float s_s2[8][DLS];
    __shared__ float s_vv[DLS];
    __shared__ float s_logit[8], s_coef[NE];

    int n = blockIdx.x, b = n >> 11, c = threadIdx.x;
    int w = c >> 5, lane = c & 31;
    float alpha = g_sc[b * 2], gamma = g_sc[b * 2 + 1];

    float efv[8];
#pragma unroll
    for (int e = 0; e < 8; e++) efv[e] = g_ef[(size_t)n * DIM + e * DLS + c];
    const float* qb = g_qkv + (size_t)n * 8 * 384;
#pragma unroll
    for (int e = 0; e < 8; e++) {
        s_q[e][c] = qb[e * 384 + c];
        s_k[1 + e][c] = qb[e * 384 + 128 + c];
        s_v[1 + e][c] = qb[e * 384 + 256 + c];
    }
    s_k[0][c] = g_k0[b * DLS + c];
    s_v[0][c] = g_v0[b * DLS + c];
    s_vv[c] = g_vv[b * DLS + c];
    __syncthreads();

    if (lane < 8) {
        int h = w;
        const float scale = 0.17677669529663688f;
        float qreg[HDV];
#pragma unroll
        for (int dd = 0; dd < HDV; dd++) qreg[dd] = s_q[lane][h * HDV + dd];
        float sc[S9];
#pragma unroll
        for (int j = 0; j < S9; j++) {
            float s = 0.f;
#pragma unroll
            for (int dd = 0; dd < HDV; dd++) s += qreg[dd] * s_k[j][h * HDV + dd];
            sc[j] = s * scale;
        }
        float m = sc[0];
#pragma unroll
        for (int j = 1; j < S9; j++) m = fmaxf(m, sc[j]);
        float ssum = 0.f;
#pragma unroll
        for (int j = 0; j < S9; j++) { sc[j] = expf(sc[j] - m); ssum += sc[j]; }
        float inv = 1.0f / ssum;
#pragma unroll
        for (int dd = 0; dd < HDV; dd++) {
            float o = 0.f;
#pragma unroll
            for (int j = 0; j < S9; j++) o += sc[j] * s_v[j][h * HDV + dd];
            s_oT[h * HDV + dd][lane] = o * inv;
        }
    }
    __syncthreads();

    {
        float seqv[8];
#pragma unroll
        for (int e = 0; e < 8; e++) seqv[e] = efv[e] + pos[e * DLS + c];
        unsigned long long po[4] = {};
#pragma unroll 2
        for (int d = 0; d < DLS; d++) {
            unsigned long long wp = bcast2(g_wt_out[d * DLS + c]);
            const unsigned long long* sp = (const unsigned long long*)&s_oT[d][0];
#pragma unroll
            for (int p = 0; p < 4; p++) fma2(po[p], sp[p], wp);
        }
        float bo = aob[c];
#pragma unroll
        for (int p = 0; p < 4; p++) {
            float lo, hi;
            unpack2(lo, hi, po[p]);
            s_s2[2 * p][c] = lo + bo + seqv[2 * p];
            s_s2[2 * p + 1][c] = hi + bo + seqv[2 * p + 1];
        }
    }
    __syncthreads();

    for (int r = w; r < 8; r += 4) {
        float s = 0.f, q = 0.f, t1 = 0.f;
#pragma unroll
        for (int k = 0; k < 4; k++) {
            float v = s_s2[r][lane + 32 * k];
            float vv = s_vv[lane + 32 * k];
            s += v;
            q += v * v;
            t1 += v * vv;
        }
#pragma unroll
        for (int o = 16; o > 0; o >>= 1) {
            s += __shfl_down_sync(0xffffffffu, s, o);
            q += __shfl_down_sync(0xffffffffu, q, o);
            t1 += __shfl_down_sync(0xffffffffu, t1, o);
        }
        if (lane == 0) {
            float mu = s * (1.0f / 128.0f);
            float var = q * (1.0f / 128.0f) - mu * mu;
            float rs = rsqrtf(var + 1e-5f);
            s_logit[r] = (rs * (t1 - mu * alpha) + gamma) * 0.08838834764831845f;
        }
    }
    __syncthreads();

    if (c == 0) {
        float p[NE];
        float m = -1e30f;
#pragma unroll
        for (int e = 0; e < NE; e++) m = fmaxf(m, s_logit[e]);
        float sum = 0.f;
#pragma unroll
        for (int e = 0; e < NE; e++) { p[e] = expf(s_logit[e] - m); sum += p[e]; }
        float inv = 1.0f / sum;
#pragma unroll
        for (int e = 0; e < NE; e++) {
            p[e] *= inv;
            g_probs[n * NE + e] = p[e];
            s_coef[e] = 0.f;
        }
        int sel[3];
        float tw[3];
        bool used[NE] = {};
#pragma unroll
        for (int t = 0; t < 3; t++) {
            int bi = 0;
            float bv = -1.f;
#pragma unroll
            for (int e = 0; e < NE; e++)
                if (!used[e] && p[e] > bv) { bv = p[e]; bi = e; }
            used[bi] = true;
            sel[t] = bi;
            tw[t] = bv;
        }
        float tinv = 1.0f / (tw[0] + tw[1] + tw[2]);
#pragma unroll
        for (int t = 0; t < 3; t++) s_coef[sel[t]] = tw[t] * tinv;
#pragma unroll
        for (int e = 0; e < NE; e++) g_coef[n * NE + e] = s_coef[e];
    }
    __syncthreads();

#pragma unroll
    for (int e = 0; e < NE; e++) {
        size_t idx = (size_t)n * DIM + e * DLS + c;
        float a = s_coef[e] * gelu_f(efv[e]);
        __half h = __float2half(a);
        g_ah[idx] = h;
        g_al[idx] = __float2half(a - __half2float(h));
    }
}

// ---------------- aux loss ---------------------------------------------------
__global__ void k_aux(float* __restrict__ out) {
    __shared__ float sp[256 * 8];
    __shared__ float sc2[256 * 8];
    int tid = threadIdx.x;
    float ps[NE], cs[NE];
#pragma unroll
    for (int e = 0; e < NE; e++) { ps[e] = 0.f; cs[e] = 0.f; }
    for (int nn = tid; nn < NTOK; nn += 256) {
#pragma unroll
        for (int e = 0; e < NE; e++) {
            ps[e] += g_probs[nn * NE + e];
            cs[e] += (g_coef[nn * NE + e] > 0.f) ? 1.0f : 0.0f;
        }
    }
#pragma unroll
    for (int e = 0; e < NE; e++) {
        sp[e * 256 + tid] = ps[e];
        sc2[e * 256 + tid] = cs[e];
    }
    __syncthreads();
    if (tid < NE) {
        float a = 0.f, bsum = 0.f;
        for (int i = 0; i < 256; i++) {
            a += sp[tid * 256 + i];
            bsum += sc2[tid * 256 + i];
        }
        sp[tid] = a;
        sc2[tid] = bsum;
    }
    __syncthreads();
    if (tid == 0) {
        float aux = 0.f;
        for (int e = 0; e < NE; e++)
            aux += (sp[e] * (1.0f / NTOK)) * (sc2[e] * (1.0f / NTOK));
        out[(size_t)NTOK * DIM] = 8.0f * aux;
    }
}

// ---------------- launch -----------------------------------------------------
extern "C" void kernel_launch(void* const* d_in, const int* in_sizes, int n_in,
                              void* d_out, int out_size) {
    const float* x    = (const float*)d_in[0];
    const float* wdn  = (const float*)d_in[1];
    const float* pos  = (const float*)d_in[2];
    const float* gpw  = (const float*)d_in[3];
    const float* gpb  = (const float*)d_in[4];
    const float* aiw  = (const float*)d_in[5];
    const float* aib  = (const float*)d_in[6];
    const float* aow  = (const float*)d_in[7];
    const float* aob  = (const float*)d_in[8];
    const float* nw   = (const float*)d_in[9];
    const float* nb   = (const float*)d_in[10];
    const float* rq1w = (const float*)d_in[11];
    const float* rq1b = (const float*)d_in[12];
    const float* rqlnw= (const float*)d_in[13];
    const float* rqlnb= (const float*)d_in[14];
    const float* rq2w = (const float*)d_in[15];
    const float* rq2b = (const float*)d_in[16];
    const float* rkw  = (const float*)d_in[17];
    const float* rkb  = (const float*)d_in[18];
    const float* wup  = (const float*)d_in[19];
    float* out = (float*)d_out;

    const int SMEM = 3 * 65536;  // 3 stages x (A0,A1,B0,B1 tiles)
    cudaFuncSetAttribute(k_gemm1, cudaFuncAttributeMaxDynamicSharedMemorySize, SMEM);
    cudaFuncSetAttribute(k_qkvg, cudaFuncAttributeMaxDynamicSharedMemorySize, SMEM);
    cudaFuncSetAttribute(k_gemm2, cudaFuncAttributeMaxDynamicSharedMemorySize, SMEM);

    k_prep<<<192, 256>>>(aow, rkw, aiw);
    k_split2_x<<<8192, 256>>>(x);
    k_split2_w1<<<1024, 256>>>(wdn);
    k_tsplit2_wup<<<dim3(32, 32), dim3(32, 8)>>>(wup);
    k_colmean<<<dim3(16, BBATCH), 256>>>(x);
    k_gctx_rq2<<<BBATCH, 1024>>>(gpw, gpb, rq1w, rq1b, rqlnw, rqlnb, rq2w, rq2b,
                                 aiw, aib, nw, nb, rkb);
    k_gemm1<<<dim3(8, 64), 256, SMEM>>>(pos);
    k_qkvg<<<dim3(3, 512), 256, SMEM>>>(aib);
    k_attn<<<NTOK, 128>>>(pos, aob);
    k_gemm2<<<dim3(8, 64), 256, SMEM>>>(out);
    k_aux<<<1, 256>>>(out);
}

// round 17
// speedup vs baseline: 1.7098x; 1.0603x over previous
#include <cuda_runtime.h>
#include <cuda_fp16.h>
#include <math.h>

#define NTOK 8192
#define DIM  1024
#define DLS  128
#define NE   8
#define HDV  32
#define TT   2048
#define BBATCH 4
#define S9   9
#define INV512 (1.0f / 512.0f)

// ---------------- scratch ----------------------------------------------------
__device__ float g_ef[NTOK * DIM];
__device__ float g_qkv[NTOK * NE * 384];
__device__ float g_xmean[BBATCH * DIM];
__device__ float g_gctx[BBATCH * DLS];
__device__ float g_k0[BBATCH * DLS];
__device__ float g_v0[BBATCH * DLS];
__device__ float g_vv[BBATCH * DLS];
__device__ float g_sc[BBATCH * 2];
__device__ float g_probs[NTOK * NE];
__device__ float g_coef[NTOK * NE];
__device__ float g_wt_out[DLS * DLS];
__device__ float g_wt_rk[DLS * DLS];

// sparse-GEMM2 routing structures
__device__ int   g_cnt[NE];
__device__ int   g_tok[NE * NTOK];
__device__ int   g_myslot[NTOK * 4];
__device__ float g_part[(size_t)NE * NTOK * 1024];  // full slot address space

__device__ __align__(16) __half g_xh[NTOK * DIM];
__device__ __align__(16) __half g_xl[NTOK * DIM];
__device__ __align__(16) __half g_w1h[DIM * DIM];
__device__ __align__(16) __half g_w1l[DIM * DIM];
__device__ __align__(16) __half g_sh[NTOK * DIM];
__device__ __align__(16) __half g_sl[NTOK * DIM];
__device__ __align__(16) __half g_aih[384 * DLS];
__device__ __align__(16) __half g_ail[384 * DLS];
__device__ __align__(16) __half g_ah[NTOK * DIM];
__device__ __align__(16) __half g_al[NTOK * DIM];
__device__ __align__(16) __half g_w2h[DIM * DIM];
__device__ __align__(16) __half g_w2l[DIM * DIM];

__device__ __forceinline__ float gelu_f(float x) {
    return 0.5f * x * (1.0f + erff(x * 0.70710678118654752440f));
}

// ---------------- PTX helpers ------------------------------------------------
__device__ __forceinline__ unsigned smem_u32(const void* p) {
    unsigned a;
    asm("{ .reg .u64 t; cvta.to.shared.u64 t, %1; cvt.u32.u64 %0, t; }"
        : "=r"(a) : "l"(p));
    return a;
}
__device__ __forceinline__ void cp16(unsigned d, const void* g) {
    asm volatile("cp.async.cg.shared.global [%0], [%1], 16;" :: "r"(d), "l"(g));
}
__device__ __forceinline__ void ldm_x4(unsigned* r, unsigned addr) {
    asm volatile("ldmatrix.sync.aligned.m8n8.x4.shared.b16 {%0,%1,%2,%3}, [%4];"
                 : "=r"(r[0]), "=r"(r[1]), "=r"(r[2]), "=r"(r[3]) : "r"(addr));
}
__device__ __forceinline__ void mma16816(float* d, const unsigned* a,
                                         unsigned b0, unsigned b1) {
    asm volatile(
        "mma.sync.aligned.m16n8k16.row.col.f32.f16.f16.f32 "
        "{%0,%1,%2,%3}, {%4,%5,%6,%7}, {%8,%9}, {%0,%1,%2,%3};"
        : "+f"(d[0]), "+f"(d[1]), "+f"(d[2]), "+f"(d[3])
        : "r"(a[0]), "r"(a[1]), "r"(a[2]), "r"(a[3]), "r"(b0), "r"(b1));
}
__device__ __forceinline__ void fma2(unsigned long long& d, unsigned long long a,
                                     unsigned long long b) {
    asm("fma.rn.f32x2 %0, %1, %2, %0;" : "+l"(d) : "l"(a), "l"(b));
}
__device__ __forceinline__ unsigned long long bcast2(float x) {
    unsigned long long r;
    asm("mov.b64 %0, {%1, %1};" : "=l"(r) : "f"(x));
    return r;
}
__device__ __forceinline__ void unpack2(float& lo, float& hi,
                                        unsigned long long v) {
    asm("mov.b64 {%0, %1}, %2;" : "=f"(lo), "=f"(hi) : "l"(v));
}

// ---------------- shared-operand split-GEMM core (dense) ---------------------
template <int KCH, int STRIDE, typename E>
__device__ __forceinline__ void gemm_run(const __half* __restrict__ A0p,
                                         const __half* __restrict__ A1p,
                                         const __half* __restrict__ B0p,
                                         const __half* __restrict__ B1p,
                                         E epi) {
    extern __shared__ __align__(128) char smem[];
    int tid = threadIdx.x, lane = tid & 31, warp = tid >> 5;
    int n0 = blockIdx.x * 128, m0 = blockIdx.y * 128;
    int wm = (warp & 1) * 64, wn = (warp >> 1) * 32;
    unsigned sbase = smem_u32(smem);
    float acc[4][4][4] = {};

    auto load = [&](int ch, int s) {
        int k0 = ch * 64;
        unsigned st = sbase + (unsigned)s * 65536u;
#pragma unroll
        for (int i = 0; i < 4; i++) {
            int cid = tid + (i << 8);
            int r = cid >> 3, c = cid & 7;
            unsigned off = (unsigned)(r * 128 + ((c ^ (r & 7)) << 4));
            cp16(st + off, (const char*)(A0p + (size_t)(m0 + r) * STRIDE + k0) + c * 16);
            cp16(st + 16384u + off, (const char*)(A1p + (size_t)(m0 + r) * STRIDE + k0) + c * 16);
            cp16(st + 32768u + off, (const char*)(B0p + (size_t)(n0 + r) * STRIDE + k0) + c * 16);
            cp16(st + 49152u + off, (const char*)(B1p + (size_t)(n0 + r) * STRIDE + k0) + c * 16);
        }
        asm volatile("cp.async.commit_group;" ::: "memory");
    };

    load(0, 0);
    if (KCH > 1) load(1, 1);
#pragma unroll 1
    for (int t = 0; t < KCH; t++) {
        if (t + 1 < KCH) {
            asm volatile("cp.async.wait_group 1;" ::: "memory");
        } else {
            asm volatile("cp.async.wait_group 0;" ::: "memory");
        }
        __syncthreads();
        if (t + 2 < KCH) load(t + 2, (t + 2) % 3);
        unsigned st = sbase + (unsigned)(t % 3) * 65536u;
        unsigned sa0 = st, sa1 = st + 16384u, sb0 = st + 32768u,
                 sb1 = st + 49152u;
#pragma unroll
        for (int ks = 0; ks < 4; ks++) {
            int clo = ks * 2;
            unsigned a0[4][4], a1[4][4], b0[2][4], b1[2][4];
#pragma unroll
            for (int g = 0; g < 4; g++) {
                int row = wm + g * 16 + (lane & 15);
                int c = clo + (lane >> 4);
                unsigned off = (unsigned)(row * 128 + ((c ^ (row & 7)) << 4));
                ldm_x4(a0[g], sa0 + off);
            }
#pragma unroll
            for (int h = 0; h < 2; h++) {
                int row = wn + h * 16 + ((lane >> 4) << 3) + (lane & 7);
                int c = clo + ((lane >> 3) & 1);
                unsigned off = (unsigned)(row * 128 + ((c ^ (row & 7)) << 4));
                ldm_x4(b0[h], sb0 + off);
                ldm_x4(b1[h], sb1 + off);
            }
#pragma unroll
            for (int g = 0; g < 4; g++) {
                int row = wm + g * 16 + (lane & 15);
                int c = clo + (lane >> 4);
                unsigned off = (unsigned)(row * 128 + ((c ^ (row & 7)) << 4));
                ldm_x4(a1[g], sa1 + off);
            }
#pragma unroll
            for (int i = 0; i < 4; i++)
#pragma unroll
                for (int j = 0; j < 4; j++) {
                    const unsigned* f0 = &b0[j >> 1][(j & 1) * 2];
                    const unsigned* f1 = &b1[j >> 1][(j & 1) * 2];
                    mma16816(acc[i][j], a0[i], f0[0], f0[1]);
                    mma16816(acc[i][j], a0[i], f1[0], f1[1]);
                    mma16816(acc[i][j], a1[i], f0[0], f0[1]);
                }
        }
    }
#pragma unroll
    for (int i = 0; i < 4; i++) {
        int row = m0 + wm + i * 16 + (lane >> 2);
#pragma unroll
        for (int j = 0; j < 4; j++)
            epi(row, n0 + wn + j * 8 + (lane & 3) * 2, acc[i][j]);
    }
}

__device__ __forceinline__ __half2 mk_h(float a, float b) {
    return __halves2half2(__float2half(a), __float2half(b));
}
__device__ __forceinline__ __half2 mk_l(float a, __half ha, float b, __half hb) {
    return __halves2half2(__float2half(a - __half2float(ha)),
                          __float2half(b - __half2float(hb)));
}

// GEMM1: ef = x @ w_down^T; also emit fp16 split of (ef + pos)
__global__ void __launch_bounds__(256) k_gemm1(const float* __restrict__ pos) {
    gemm_run<16, 1024>(g_xh, g_xl, g_w1h, g_w1l,
                       [&](int row, int col, const float* a) {
#pragma unroll
        for (int hh = 0; hh < 2; hh++) {
            int r = row + hh * 8;
            float v0 = a[hh * 2] * INV512, v1 = a[hh * 2 + 1] * INV512;
            size_t o = (size_t)r * 1024 + col;
            *(float2*)(g_ef + o) = make_float2(v0, v1);
            float2 pv = *(const float2*)(pos + col);
            float s0 = v0 + pv.x, s1 = v1 + pv.y;
            __half2 h = mk_h(s0, s1);
            *(__half2*)(g_sh + o) = h;
            *(__half2*)(g_sl + o) = mk_l(s0, __low2half(h), s1, __high2half(h));
        }
    });
}

// qkv GEMM: (8N,128) seq @ attn_in_w^T -> (8N,384) + bias
__global__ void __launch_bounds__(256) k_qkvg(const float* __restrict__ aib) {
    gemm_run<2, 128>(g_sh, g_sl, g_aih, g_ail,
                     [&](int row, int col, const float* a) {
        float2 bv = *(const float2*)(aib + col);
#pragma unroll
        for (int hh = 0; hh < 2; hh++) {
            int r = row + hh * 8;
            *(float2*)(g_qkv + (size_t)r * 384 + col) =
                make_float2(a[hh * 2] * INV512 + bv.x,
                            a[hh * 2 + 1] * INV512 + bv.y);
        }
    });
}

// ---------------- sparse GEMM2: per-expert gathered rows ---------------------
__global__ void __launch_bounds__(256) k_gemm2s() {
    extern __shared__ __align__(128) char smem[];
    int e = blockIdx.z;
    int cnt = g_cnt[e];
    int m0 = blockIdx.y * 128;
    if (m0 >= cnt) return;
    int n0 = blockIdx.x * 128;
    int tid = threadIdx.x, lane = tid & 31, warp = tid >> 5;
    int wm = (warp & 1) * 64, wn = (warp >> 1) * 32;
    unsigned sbase = smem_u32(smem);
    float acc[4][4][4] = {};
    const int* toks = g_tok + e * NTOK;

    auto load = [&](int ch, int s) {
        int k0 = e * 128 + ch * 64;
        unsigned st = sbase + (unsigned)s * 65536u;
#pragma unroll
        for (int i = 0; i < 4; i++) {
            int cid = tid + (i << 8);
            int r = cid >> 3, c = cid & 7;
            unsigned off = (unsigned)(r * 128 + ((c ^ (r & 7)) << 4));
            int mr = m0 + r;
            if (mr >= cnt) mr = cnt - 1;
            int tk = toks[mr];
            cp16(st + off, (const char*)(g_ah + (size_t)tk * 1024 + k0) + c * 16);
            cp16(st + 16384u + off, (const char*)(g_al + (size_t)tk * 1024 + k0) + c * 16);
            cp16(st + 32768u + off, (const char*)(g_w2h + (size_t)(n0 + r) * 1024 + k0) + c * 16);
            cp16(st + 49152u + off, (const char*)(g_w2l + (size_t)(n0 + r) * 1024 + k0) + c * 16);
        }
        asm volatile("cp.async.commit_group;" ::: "memory");
    };

    load(0, 0);
    load(1, 1);
#pragma unroll 1
    for (int t = 0; t < 2; t++) {
        if (t == 0) {
            asm volatile("cp.async.wait_group 1;" ::: "memory");
        } else {
            asm volatile("cp.async.wait_group 0;" ::: "memory");
        }
        __syncthreads();
        unsigned st = sbase + (unsigned)t * 65536u;
        unsigned sa0 = st, sa1 = st + 16384u, sb0 = st + 32768u,
                 sb1 = st + 49152u;
#pragma unroll
        for (int ks = 0; ks < 4; ks++) {
            int clo = ks * 2;
            unsigned a0[4][4], a1[4][4], b0[2][4], b1[2][4];
#pragma unroll
            for (int g = 0; g < 4; g++) {
                int row = wm + g * 16 + (lane & 15);
                int c = clo + (lane >> 4);
                unsigned off = (unsigned)(row * 128 + ((c ^ (row & 7)) << 4));
                ldm_x4(a0[g], sa0 + off);
                ldm_x4(a1[g], sa1 + off);
            }
#pragma unroll
            for (int h = 0; h < 2; h++) {
                int row = wn + h * 16 + ((lane >> 4) << 3) + (lane & 7);
                int c = clo + ((lane >> 3) & 1);
                unsigned off = (unsigned)(row * 128 + ((c ^ (row & 7)) << 4));
                ldm_x4(b0[h], sb0 + off);
                ldm_x4(b1[h], sb1 + off);
            }
#pragma unroll
            for (int i = 0; i < 4; i++)
#pragma unroll
                for (int j = 0; j < 4; j++) {
                    const unsigned* f0 = &b0[j >> 1][(j & 1) * 2];
                    const unsigned* f1 = &b1[j >> 1][(j & 1) * 2];
                    mma16816(acc[i][j], a0[i], f0[0], f0[1]);
                    mma16816(acc[i][j], a0[i], f1[0], f1[1]);
                    mma16816(acc[i][j], a1[i], f0[0], f0[1]);
                }
        }
        __syncthreads();
    }
#pragma unroll
    for (int i = 0; i < 4; i++) {
        int rl = wm + i * 16 + (lane >> 2);
#pragma unroll
        for (int j = 0; j < 4; j++) {
            int col = n0 + wn + j * 8 + (lane & 3) * 2;
            if (m0 + rl < cnt)
                *(float2*)(g_part + (size_t)(e * NTOK + m0 + rl) * 1024 + col) =
                    make_float2(acc[i][j][0] * INV512, acc[i][j][1] * INV512);
            if (m0 + rl + 8 < cnt)
                *(float2*)(g_part + (size_t)(e * NTOK + m0 + rl + 8) * 1024 + col) =
                    make_float2(acc[i][j][2] * INV512, acc[i][j][3] * INV512);
        }
    }
}

// out[n] = sum of token n's 3 partial rows
__global__ void __launch_bounds__(256) k_sum(float* __restrict__ out) {
    int n = blockIdx.x, c = threadIdx.x;
    int s0 = g_myslot[n * 4], s1 = g_myslot[n * 4 + 1], s2 = g_myslot[n * 4 + 2];
    const float4* p = (const float4*)g_part;
    float4 a = p[(size_t)s0 * 256 + c];
    float4 b = p[(size_t)s1 * 256 + c];
    float4 d = p[(size_t)s2 * 256 + c];
    ((float4*)out)[(size_t)n * 256 + c] =
        make_float4(a.x + b.x + d.x, a.y + b.y + d.y, a.z + b.z + d.z,
                    a.w + b.w + d.w);
}

// ---------------- split kernels ----------------------------------------------
__device__ __forceinline__ void split2_core(float4 v, float scale,
                                            __half* dh, __half* dl, size_t i) {
    float vs[4] = {v.x * scale, v.y * scale, v.z * scale, v.w * scale};
    __half2 h0 = mk_h(vs[0], vs[1]), h1 = mk_h(vs[2], vs[3]);
    ((__half2*)dh)[2 * i] = h0;
    ((__half2*)dh)[2 * i + 1] = h1;
    ((__half2*)dl)[2 * i] = mk_l(vs[0], __low2half(h0), vs[1], __high2half(h0));
    ((__half2*)dl)[2 * i + 1] = mk_l(vs[2], __low2half(h1), vs[3], __high2half(h1));
}
__global__ void k_split2_x(const float* __restrict__ x) {
    size_t i = (size_t)blockIdx.x * blockDim.x + threadIdx.x;
    split2_core(((const float4*)x)[i], 1.0f, g_xh, g_xl, i);
}
__global__ void k_split2_w1(const float* __restrict__ w) {
    size_t i = (size_t)blockIdx.x * blockDim.x + threadIdx.x;
    split2_core(((const float4*)w)[i], 512.0f, g_w1h, g_w1l, i);
}
__global__ void k_tsplit2_wup(const float* __restrict__ wup) {
    __shared__ float tile[32][33];
    int k0 = blockIdx.y * 32, m0 = blockIdx.x * 32;
    int tx = threadIdx.x, ty = threadIdx.y;
#pragma unroll
    for (int i = 0; i < 32; i += 8)
        tile[ty + i][tx] = wup[(size_t)(k0 + ty + i) * 1024 + m0 + tx];
    __syncthreads();
#pragma unroll
    for (int i = 0; i < 32; i += 8) {
        float v = tile[tx][ty + i] * 512.0f;
        __half h = __float2half(v);
        size_t o = (size_t)(m0 + ty + i) * 1024 + k0 + tx;
        g_w2h[o] = h;
        g_w2l[o] = __float2half(v - __half2float(h));
    }
}

// ---------------- prep -------------------------------------------------------
__global__ void k_prep(const float* __restrict__ aow,
                       const float* __restrict__ rkw,
                       const float* __restrict__ aiw) {
    int idx = blockIdx.x * blockDim.x + threadIdx.x;
    if (idx < NE) g_cnt[idx] = 0;
    if (idx < BBATCH * DIM) g_xmean[idx] = 0.0f;
    if (idx < DLS * DLS) {
        g_wt_out[(idx % DLS) * DLS + idx / DLS] = aow[idx];
        g_wt_rk[(idx % DLS) * DLS + idx / DLS] = rkw[idx];
    }
    if (idx < 384 * DLS) {
        float v = aiw[idx] * 512.0f;
        __half h = __float2half(v);
        g_aih[idx] = h;
        g_ail[idx] = __float2half(v - __half2float(h));
    }
}

__global__ void k_colmean(const float* __restrict__ x) {
    int b = blockIdx.y, tc = blockIdx.x, tid = threadIdx.x;
    const float* xb = x + (size_t)b * TT * DIM + (size_t)tc * 128 * DIM;
    float acc[4] = {0.f, 0.f, 0.f, 0.f};
    for (int t = 0; t < 128; t++) {
        const float* row = xb + (size_t)t * DIM + tid;
#pragma unroll
        for (int i = 0; i < 4; i++) acc[i] += row[i * 256];
    }
#pragma unroll
    for (int i = 0; i < 4; i++)
        atomicAdd(&g_xmean[b * DIM + tid + i * 256], acc[i]);
}

// ---------------- gctx + k0/v0 + routing constants ---------------------------
__global__ void __launch_bounds__(1024) k_gctx_rq2(
    const float* __restrict__ gpw, const float* __restrict__ gpb,
    const float* __restrict__ rq1w, const float* __restrict__ rq1b,
    const float* __restrict__ rqlnw, const float* __restrict__ rqlnb,
    const float* __restrict__ rq2w, const float* __restrict__ rq2b,
    const float* __restrict__ aiw, const float* __restrict__ aib,
    const float* __restrict__ nw, const float* __restrict__ nb,
    const float* __restrict__ rkb) {
    __shared__ float sx[DIM];
    __shared__ float sg[DLS], st[DLS], sh[DLS];
    __shared__ float srq[DLS], su[DLS], svv[DLS];
    __shared__ float sred[8];
    int b = blockIdx.x, t = threadIdx.x;
    sx[t] = g_xmean[b * DIM + t] * (1.0f / TT);
    __syncthreads();
    int c = t >> 3, seg = t & 7;
    {
        float acc = 0.f;
        const float4* w4 = (const float4*)(gpw + (size_t)c * DIM + seg * 128);
        const float4* x4 = (const float4*)(sx + seg * 128);
#pragma unroll 8
        for (int i = 0; i < 32; i++) {
            float4 w = w4[i], xx = x4[i];
            acc += w.x * xx.x + w.y * xx.y + w.z * xx.z + w.w * xx.w;
        }
        acc += __shfl_down_sync(0xffffffffu, acc, 4, 8);
        acc += __shfl_down_sync(0xffffffffu, acc, 2, 8);
        acc += __shfl_down_sync(0xffffffffu, acc, 1, 8);
        if (seg == 0) {
            float gc = acc + gpb[c];
            sg[c] = gc;
            g_gctx[b * DLS + c] = gc;
        }
    }
    __syncthreads();
    {
        float acc = 0.f;
        const float4* w4 = (const float4*)(rq1w + (size_t)c * DLS + seg * 16);
        const float4* x4 = (const float4*)(sg + seg * 16);
#pragma unroll
        for (int i = 0; i < 4; i++) {
            float4 w = w4[i], xx = x4[i];
            acc += w.x * xx.x + w.y * xx.y + w.z * xx.z + w.w * xx.w;
        }
        acc += __shfl_down_sync(0xffffffffu, acc, 4, 8);
        acc += __shfl_down_sync(0xffffffffu, acc, 2, 8);
        acc += __shfl_down_sync(0xffffffffu, acc, 1, 8);
        if (seg == 0) st[c] = acc + rq1b[c];
    }
    {
        float acc = 0.f;
        const float4* w4 = (const float4*)(aiw + (size_t)(DLS + c) * DLS + seg * 16);
        const float4* x4 = (const float4*)(sg + seg * 16);
#pragma unroll
        for (int i = 0; i < 4; i++) {
            float4 w = w4[i], xx = x4[i];
            acc += w.x * xx.x + w.y * xx.y + w.z * xx.z + w.w * xx.w;
        }
        acc += __shfl_down_sync(0xffffffffu, acc, 4, 8);
        acc += __shfl_down_sync(0xffffffffu, acc, 2, 8);
        acc += __shfl_down_sync(0xffffffffu, acc, 1, 8);
        if (seg == 0) g_k0[b * DLS + c] = acc + aib[DLS + c];
    }
    {
        float acc = 0.f;
        const float4* w4 = (const float4*)(aiw + (size_t)(2 * DLS + c) * DLS + seg * 16);
        const float4* x4 = (const float4*)(sg + seg * 16);
#pragma unroll
        for (int i = 0; i < 4; i++) {
            float4 w = w4[i], xx = x4[i];
            acc += w.x * xx.x + w.y * xx.y + w.z * xx.z + w.w * xx.w;
        }
        acc += __shfl_down_sync(0xffffffffu, acc, 4, 8);
        acc += __shfl_down_sync(0xffffffffu, acc, 2, 8);
        acc += __shfl_down_sync(0xffffffffu, acc, 1, 8);
        if (seg == 0) g_v0[b * DLS + c] = acc + aib[2 * DLS + c];
    }
    __syncthreads();
    if (t < DLS) {
        float v = st[t];
        float s = v, q = v * v;
#pragma unroll
        for (int o = 16; o > 0; o >>= 1) {
            s += __shfl_down_sync(0xffffffffu, s, o);
            q += __shfl_down_sync(0xffffffffu, q, o);
        }
        if ((t & 31) == 0) { sred[t >> 5] = s; sred[4 + (t >> 5)] = q; }
    }
    __syncthreads();
    if (t < DLS) {
        float s = sred[0] + sred[1] + sred[2] + sred[3];
        float q = sred[4] + sred[5] + sred[6] + sred[7];
        float mu = s * (1.0f / 128.0f);
        float var = q * (1.0f / 128.0f) - mu * mu;
        float h = (st[t] - mu) * rsqrtf(var + 1e-5f) * rqlnw[t] + rqlnb[t];
        sh[t] = gelu_f(h);
    }
    __syncthreads();
    {
        float acc = 0.f;
        const float4* w4 = (const float4*)(rq2w + (size_t)c * DLS + seg * 16);
        const float4* x4 = (const float4*)(sh + seg * 16);
#pragma unroll
        for (int i = 0; i < 4; i++) {
            float4 w = w4[i], xx = x4[i];
            acc += w.x * xx.x + w.y * xx.y + w.z * xx.z + w.w * xx.w;
        }
        acc += __shfl_down_sync(0xffffffffu, acc, 4, 8);
        acc += __shfl_down_sync(0xffffffffu, acc, 2, 8);
        acc += __shfl_down_sync(0xffffffffu, acc, 1, 8);
        if (seg == 0) srq[c] = acc + rq2b[c];
    }
    __syncthreads();
    {
        float acc = 0.f;
        const float4* w4 = (const float4*)(g_wt_rk + (size_t)c * DLS + seg * 16);
        const float4* x4 = (const float4*)(srq + seg * 16);
#pragma unroll
        for (int i = 0; i < 4; i++) {
            float4 w = w4[i], xx = x4[i];
            acc += w.x * xx.x + w.y * xx.y + w.z * xx.z + w.w * xx.w;
        }
        acc += __shfl_down_sync(0xffffffffu, acc, 4, 8);
        acc += __shfl_down_sync(0xffffffffu, acc, 2, 8);
        acc += __shfl_down_sync(0xffffffffu, acc, 1, 8);
        if (seg == 0) {
            su[c] = acc;
            float vvv = nw[c] * acc;
            svv[c] = vvv;
            g_vv[b * DLS + c] = vvv;
        }
    }
    __syncthreads();
    if (t < 32) {
        float a = 0.f, bb = 0.f, ss = 0.f;
#pragma unroll
        for (int k = 0; k < 4; k++) {
            int d = t + k * 32;
            a += svv[d];
            bb += nb[d] * su[d];
            ss += srq[d] * rkb[d];
        }
#pragma unroll
        for (int o = 16; o > 0; o >>= 1) {
            a += __shfl_down_sync(0xffffffffu, a, o);
            bb += __shfl_down_sync(0xffffffffu, bb, o);
            ss += __shfl_down_sync(0xffffffffu, ss, o);
        }
        if (t == 0) {
            g_sc[b * 2] = a;
            g_sc[b * 2 + 1] = bb + ss;
        }
    }
}

// ---------------- per-token: attention + router + list build -----------------
__global__ void __launch_bounds__(128) k_attn(
    const float* __restrict__ pos, const float* __restrict__ aob) {
    __shared__ float s_q[8][129];
    __shared__ float s_k[S9][DLS];
    __shared__ float s_v[S9][DLS];
    __shared__ __align__(16) float s_oT[DLS][10];
    __shared__ float s_s2[8][DLS];
    __shared__ float s_vv[DLS];
    __shared__ float s_logit[8], s_coef[NE];

    int n = blockIdx.x, b = n >> 11, c = threadIdx.x;
    int w = c >> 5, lane = c & 31;
    float alpha = g_sc[b * 2], gamma = g_sc[b * 2 + 1];

    float efv[8];
#pragma unroll
    for (int e = 0; e < 8; e++) efv[e] = g_ef[(size_t)n * DIM + e * DLS + c];
    const float* qb = g_qkv + (size_t)n * 8 * 384;
#pragma unroll
    for (int e = 0; e < 8; e++) {
        s_q[e][c] = qb[e * 384 + c];
        s_k[1 + e][c] = qb[e * 384 + 128 + c];
        s_v[1 + e][c] = qb[e * 384 + 256 + c];
    }
    s_k[0][c] = g_k0[b * DLS + c];
    s_v[0][c] = g_v0[b * DLS + c];
    s_vv[c] = g_vv[b * DLS + c];
    __syncthreads();

    if (lane < 8) {
        int h = w;
        const float scale = 0.17677669529663688f;
        float qreg[HDV];
#pragma unroll
        for (int dd = 0; dd < HDV; dd++) qreg[dd] = s_q[lane][h * HDV + dd];
        float sc[S9];
#pragma unroll
        for (int j = 0; j < S9; j++) {
            float s = 0.f;
#pragma unroll
            for (int dd = 0; dd < HDV; dd++) s += qreg[dd] * s_k[j][h * HDV + dd];
            sc[j] = s * scale;
        }
        float m = sc[0];
#pragma unroll
        for (int j = 1; j < S9; j++) m = fmaxf(m, sc[j]);
        float ssum = 0.f;
#pragma unroll
        for (int j = 0; j < S9; j++) { sc[j] = expf(sc[j] - m); ssum += sc[j]; }
        float inv = 1.0f / ssum;
#pragma unroll
        for (int dd = 0; dd < HDV; dd++) {
            float o = 0.f;
#pragma unroll
            for (int j = 0; j < S9; j++) o += sc[j] * s_v[j][h * HDV + dd];
            s_oT[h * HDV + dd][lane] = o * inv;
        }
    }
    __syncthreads();

    {
        float seqv[8];
#pragma unroll
        for (int e = 0; e < 8; e++) seqv[e] = efv[e] + pos[e * DLS + c];
        unsigned long long po[4] = {};
#pragma unroll 2
        for (int d = 0; d < DLS; d++) {
            unsigned long long wp = bcast2(g_wt_out[d * DLS + c]);
            const unsigned long long* sp = (const unsigned long long*)&s_oT[d][0];
#pragma unroll
            for (int p = 0; p < 4; p++) fma2(po[p], sp[p], wp);
        }
        float bo = aob[c];
#pragma unroll
        for (int p = 0; p < 4; p++) {
            float lo, hi;
            unpack2(lo, hi, po[p]);
            s_s2[2 * p][c] = lo + bo + seqv[2 * p];
            s_s2[2 * p + 1][c] = hi + bo + seqv[2 * p + 1];
        }
    }
    __syncthreads();

    for (int r = w; r < 8; r += 4) {
        float s = 0.f, q = 0.f, t1 = 0.f;
#pragma unroll
        for (int k = 0; k < 4; k++) {
            float v = s_s2[r][lane + 32 * k];
            float vv = s_vv[lane + 32 * k];
            s += v;
            q += v * v;
            t1 += v * vv;
        }
#pragma unroll
        for (int o = 16; o > 0; o >>= 1) {
            s += __shfl_down_sync(0xffffffffu, s, o);
            q += __shfl_down_sync(0xffffffffu, q, o);
            t1 += __shfl_down_sync(0xffffffffu, t1, o);
        }
        if (lane == 0) {
            float mu = s * (1.0f / 128.0f);
            float var = q * (1.0f / 128.0f) - mu * mu;
            float rs = rsqrtf(var + 1e-5f);
            s_logit[r] = (rs * (t1 - mu * alpha) + gamma) * 0.08838834764831845f;
        }
    }
    __syncthreads();

    if (c == 0) {
        float p[NE];
        float m = -1e30f;
#pragma unroll
        for (int e = 0; e < NE; e++) m = fmaxf(m, s_logit[e]);
        float sum = 0.f;
#pragma unroll
        for (int e = 0; e < NE; e++) { p[e] = expf(s_logit[e] - m); sum += p[e]; }
        float inv = 1.0f / sum;
#pragma unroll
        for (int e = 0; e < NE; e++) {
            p[e] *= inv;
            g_probs[n * NE + e] = p[e];
            s_coef[e] = 0.f;
        }
        int sel[3];
        float tw[3];
        bool used[NE] = {};
#pragma unroll
        for (int t = 0; t < 3; t++) {
            int bi = 0;
            float bv = -1.f;
#pragma unroll
            for (int e = 0; e < NE; e++)
                if (!used[e] && p[e] > bv) { bv = p[e]; bi = e; }
            used[bi] = true;
            sel[t] = bi;
            tw[t] = bv;
        }
        float tinv = 1.0f / (tw[0] + tw[1] + tw[2]);
#pragma unroll
        for (int t = 0; t < 3; t++) s_coef[sel[t]] = tw[t] * tinv;
#pragma unroll
        for (int e = 0; e < NE; e++) g_coef[n * NE + e] = s_coef[e];
#pragma unroll
        for (int t = 0; t < 3; t++) {
            int slot = atomicAdd(&g_cnt[sel[t]], 1);
            g_tok[sel[t] * NTOK + slot] = n;
            g_myslot[n * 4 + t] = sel[t] * NTOK + slot;
        }
    }
    __syncthreads();

#pragma unroll
    for (int e = 0; e < NE; e++) {
        size_t idx = (size_t)n * DIM + e * DLS + c;
        float a = s_coef[e] * gelu_f(efv[e]);
        __half h = __float2half(a);
        g_ah[idx] = h;
        g_al[idx] = __float2half(a - __half2float(h));
    }
}

// ---------------- aux loss ---------------------------------------------------
__global__ void k_aux(float* __restrict__ out) {
    __shared__ float sp[256 * 8];
    __shared__ float sc2[256 * 8];
    int tid = threadIdx.x;
    float ps[NE], cs[NE];
#pragma unroll
    for (int e = 0; e < NE; e++) { ps[e] = 0.f; cs[e] = 0.f; }
    for (int nn = tid; nn < NTOK; nn += 256) {
#pragma unroll
        for (int e = 0; e < NE; e++) {
            ps[e] += g_probs[nn * NE + e];
            cs[e] += (g_coef[nn * NE + e] > 0.f) ? 1.0f : 0.0f;
        }
    }
#pragma unroll
    for (int e = 0; e < NE; e++) {
        sp[e * 256 + tid] = ps[e];
        sc2[e * 256 + tid] = cs[e];
    }
    __syncthreads();
    if (tid < NE) {
        float a = 0.f, bsum = 0.f;
        for (int i = 0; i < 256; i++) {
            a += sp[tid * 256 + i];
            bsum += sc2[tid * 256 + i];
        }
        sp[tid] = a;
        sc2[tid] = bsum;
    }
    __syncthreads();
    if (tid == 0) {
        float aux = 0.f;
        for (int e = 0; e < NE; e++)
            aux += (sp[e] * (1.0f / NTOK)) * (sc2[e] * (1.0f / NTOK));
        out[(size_t)NTOK * DIM] = 8.0f * aux;
    }
}

// ---------------- launch -----------------------------------------------------
extern "C" void kernel_launch(void* const* d_in, const int* in_sizes, int n_in,
                              void* d_out, int out_size) {
    const float* x    = (const float*)d_in[0];
    const float* wdn  = (const float*)d_in[1];
    const float* pos  = (const float*)d_in[2];
    const float* gpw  = (const float*)d_in[3];
    const float* gpb  = (const float*)d_in[4];
    const float* aiw  = (const float*)d_in[5];
    const float* aib  = (const float*)d_in[6];
    const float* aow  = (const float*)d_in[7];
    const float* aob  = (const float*)d_in[8];
    const float* nw   = (const float*)d_in[9];
    const float* nb   = (const float*)d_in[10];
    const float* rq1w = (const float*)d_in[11];
    const float* rq1b = (const float*)d_in[12];
    const float* rqlnw= (const float*)d_in[13];
    const float* rqlnb= (const float*)d_in[14];
    const float* rq2w = (const float*)d_in[15];
    const float* rq2b = (const float*)d_in[16];
    const float* rkw  = (const float*)d_in[17];
    const float* rkb  = (const float*)d_in[18];
    const float* wup  = (const float*)d_in[19];
    float* out = (float*)d_out;

    const int SMEM = 3 * 65536;
    const int SMEM2 = 2 * 65536;
    cudaFuncSetAttribute(k_gemm1, cudaFuncAttributeMaxDynamicSharedMemorySize, SMEM);
    cudaFuncSetAttribute(k_qkvg, cudaFuncAttributeMaxDynamicSharedMemorySize, SMEM);
    cudaFuncSetAttribute(k_gemm2s, cudaFuncAttributeMaxDynamicSharedMemorySize, SMEM2);

    k_prep<<<192, 256>>>(aow, rkw, aiw);
    k_split2_x<<<8192, 256>>>(x);
    k_split2_w1<<<1024, 256>>>(wdn);
    k_tsplit2_wup<<<dim3(32, 32), dim3(32, 8)>>>(wup);
    k_colmean<<<dim3(16, BBATCH), 256>>>(x);
    k_gctx_rq2<<<BBATCH, 1024>>>(gpw, gpb, rq1w, rq1b, rqlnw, rqlnb, rq2w, rq2b,
                                 aiw, aib, nw, nb, rkb);
    k_gemm1<<<dim3(8, 64), 256, SMEM>>>(pos);
    k_qkvg<<<dim3(3, 512), 256, SMEM>>>(aib);
    k_attn<<<NTOK, 128>>>(pos, aob);
    k_gemm2s<<<dim3(8, 64, NE), 256, SMEM2>>>();
    k_sum<<<NTOK, 256>>>(out);
    k_aux<<<1, 256>>>(out);
}